// round 6
// baseline (speedup 1.0000x reference)
#include <cuda_runtime.h>
#include <cuda_bf16.h>
#include <cstdint>

// ---------------- problem constants ----------------
#define NMAX   200000
#define CCH    64
#define KTAPS  9
#define TN     128          // rows per block (MMA M)
#define NTHR   128
#define LEAK   0.01f
#define EPS_BN 1e-5f

// per-stage dynamic smem: Ahi 16K | Alo 16K | Bhi 8K | Blo 8K = 48K, double-buffered
#define OFF_ALO 16384
#define OFF_BHI 32768
#define OFF_BLO 40960
#define STAGE_BYTES 49152
#define DSM_BYTES (2 * STAGE_BYTES)
#define SC_STRIDE 68        // epilogue fp32 tile stride (floats)

// ---------------- scratch (no cudaMalloc allowed) ----------------
__device__ float g_bufB[(size_t)NMAX * CCH];
// interleaved split planes: [row][hi 64 bf16 | lo 64 bf16]; row nTotal = zero pad
__device__ __nv_bfloat16 g_fS[((size_t)NMAX + 1) * 128];
__device__ __nv_bfloat16 g_aS[((size_t)NMAX + 1) * 128];
__device__ __nv_bfloat16 g_wHi[4 * KTAPS * 64 * 64];  // [tensor][tap][o][c]
__device__ __nv_bfloat16 g_wLo[4 * KTAPS * 64 * 64];
__device__ __nv_bfloat16 g_biasHi[4 * 64 * 16];       // [tensor][o*16 + tap]
__device__ __nv_bfloat16 g_biasLo[4 * 64 * 16];
__device__ float g_sums [4][CCH];
__device__ float g_sumsq[4][CCH];

// ---------------- helpers ----------------
__device__ __forceinline__ uint32_t smem_u32(const void* p) {
    uint32_t a;
    asm("{ .reg .u64 t; cvta.to.shared.u64 t, %1; cvt.u32.u64 %0, t; }" : "=r"(a) : "l"(p));
    return a;
}
__device__ __forceinline__ void ldsm4(uint32_t* r, uint32_t addr) {
    asm volatile("ldmatrix.sync.aligned.m8n8.x4.shared.b16 {%0,%1,%2,%3}, [%4];"
        : "=r"(r[0]), "=r"(r[1]), "=r"(r[2]), "=r"(r[3]) : "r"(addr));
}
__device__ __forceinline__ void mma16816(float* c, const uint32_t* a, const uint32_t* b) {
    asm volatile("mma.sync.aligned.m16n8k16.row.col.f32.bf16.bf16.f32 "
        "{%0,%1,%2,%3}, {%4,%5,%6,%7}, {%8,%9}, {%0,%1,%2,%3};"
        : "+f"(c[0]), "+f"(c[1]), "+f"(c[2]), "+f"(c[3])
        : "r"(a[0]), "r"(a[1]), "r"(a[2]), "r"(a[3]), "r"(b[0]), "r"(b[1]));
}
__device__ __forceinline__ void cpa16(uint32_t dst, const void* src) {
    asm volatile("cp.async.cg.shared.global [%0], [%1], 16;" :: "r"(dst), "l"(src) : "memory");
}
__device__ __forceinline__ void bsplit(float v, uint16_t &h, uint16_t &l) {
    __nv_bfloat16 bh = __float2bfloat16(v);
    h = __bfloat16_as_ushort(bh);
    l = __bfloat16_as_ushort(__float2bfloat16(v - __bfloat162float(bh)));
}

// ---------------- aux kernels ----------------
__global__ void zero_stats_k(int nTotal) {
    const int i = threadIdx.x;   // 512
    if (i < 256) ((float*)g_sums)[i] = 0.f;
    else ((float*)g_sumsq)[i - 256] = 0.f;
#pragma unroll
    for (int j = 0; j < 4; ++j) {
        ((uint32_t*)g_biasHi)[i + j * 512] = 0u;
        ((uint32_t*)g_biasLo)[i + j * 512] = 0u;
    }
    if (i < 64)  ((uint32_t*)(g_fS + (size_t)nTotal * 128))[i] = 0u;
    else if (i < 128) ((uint32_t*)(g_aS + (size_t)nTotal * 128))[i - 64] = 0u;
}

// plain weights [9][c][o] -> planes [tensor][tap][o][c] (tensors 0 and 2)
__global__ void prep_plain_k(const float* __restrict__ w1, const float* __restrict__ w2) {
    const int t = (blockIdx.x < KTAPS) ? 0 : 2;
    const int k = blockIdx.x % KTAPS;
    const float* src = ((t == 0) ? w1 : w2) + k * 4096;
    __nv_bfloat16* dh = g_wHi + (size_t)(t * KTAPS + k) * 4096;
    __nv_bfloat16* dl = g_wLo + (size_t)(t * KTAPS + k) * 4096;
#pragma unroll
    for (int i = 0; i < 16; ++i) {
        const int j = threadIdx.x + i * 256;     // j = c*64 + o
        const int c = j >> 6, o = j & 63;
        uint16_t h, l;
        bsplit(src[j], h, l);
        dh[o * 64 + c] = __ushort_as_bfloat16(h);
        dl[o * 64 + c] = __ushort_as_bfloat16(l);
        (void)c;
    }
}

// fold BN(stage) of the INPUT into weights: W' = scale[c]*W, bias_k[o] = sum_c shift[c]*W[c,o]
__global__ void prep_fold_k(const float* __restrict__ w, int tensor, int stage,
                            const float* __restrict__ gamma,
                            const float* __restrict__ beta, float invN) {
    __shared__ float sc[64], sh[64];
    const int k = blockIdx.x, tid = threadIdx.x;
    if (tid < 64) {
        const float m = g_sums[stage][tid] * invN;
        const float v = g_sumsq[stage][tid] * invN - m * m;
        const float a = gamma[tid] * rsqrtf(v + EPS_BN);
        sc[tid] = a;
        sh[tid] = beta[tid] - m * a;
    }
    __syncthreads();
    const float* src = w + (size_t)k * 4096;
    __nv_bfloat16* dh = g_wHi + (size_t)(tensor * KTAPS + k) * 4096;
    __nv_bfloat16* dl = g_wLo + (size_t)(tensor * KTAPS + k) * 4096;
#pragma unroll
    for (int i = 0; i < 16; ++i) {
        const int j = tid + i * 256;             // j = c*64 + o
        const int c = j >> 6, o = j & 63;
        uint16_t h, l;
        bsplit(sc[c] * src[j], h, l);
        dh[o * 64 + c] = __ushort_as_bfloat16(h);
        dl[o * 64 + c] = __ushort_as_bfloat16(l);
    }
    if (tid < 64) {
        float s = 0.f;
#pragma unroll 8
        for (int c = 0; c < 64; ++c) s += sh[c] * src[c * 64 + tid];
        uint16_t h, l;
        bsplit(s, h, l);
        g_biasHi[tensor * 1024 + tid * 16 + k] = __ushort_as_bfloat16(h);
        g_biasLo[tensor * 1024 + tid * 16 + k] = __ushort_as_bfloat16(l);
    }
}

// fp32 features -> interleaved bf16 hi/lo planes (once)
__global__ __launch_bounds__(256)
void split_k(const float* __restrict__ src, __nv_bfloat16* __restrict__ dst, int nTotal) {
    const int row = blockIdx.x * 256 + threadIdx.x;
    if (row >= nTotal) return;
    const float4* s = (const float4*)(src + (size_t)row * CCH);
    uint4* d = (uint4*)(dst + (size_t)row * 128);
#pragma unroll
    for (int g = 0; g < 8; ++g) {
        const float4 v0 = s[2 * g], v1 = s[2 * g + 1];
        const float vv[8] = {v0.x, v0.y, v0.z, v0.w, v1.x, v1.y, v1.z, v1.w};
        uint16_t hh[8], ll[8];
#pragma unroll
        for (int e = 0; e < 8; ++e) bsplit(vv[e], hh[e], ll[e]);
        uint4 H, L;
        H.x = (uint32_t)hh[0] | ((uint32_t)hh[1] << 16);
        H.y = (uint32_t)hh[2] | ((uint32_t)hh[3] << 16);
        H.z = (uint32_t)hh[4] | ((uint32_t)hh[5] << 16);
        H.w = (uint32_t)hh[6] | ((uint32_t)hh[7] << 16);
        L.x = (uint32_t)ll[0] | ((uint32_t)ll[1] << 16);
        L.y = (uint32_t)ll[2] | ((uint32_t)ll[3] << 16);
        L.z = (uint32_t)ll[4] | ((uint32_t)ll[5] << 16);
        L.w = (uint32_t)ll[6] | ((uint32_t)ll[7] << 16);
        d[g] = H;
        d[8 + g] = L;
    }
}

// ---------------- main conv kernel (mma.sync bf16 3-term, cp.async pipeline) ----------------
template <bool HAS_BIAS, bool OUT_PLANES>
__global__ __launch_bounds__(NTHR)
void conv_mma_k(const __nv_bfloat16* __restrict__ src,   // [N+1][128] hi|lo
                const int* __restrict__ nbr, int wtIdx,
                float* __restrict__ dstF, __nv_bfloat16* __restrict__ dstP,
                int nTotal, int stage)
{
    extern __shared__ __align__(128) char smemc[];
    __shared__ uint4 sAV[128][2];     // validity [128 rows][16 taps] bf16
    __shared__ uint4 sBBh[128];       // bias hi [64 o][16 taps] bf16
    __shared__ uint4 sBBl[128];

    const int tid   = threadIdx.x;
    const int lane  = tid & 31;
    const int wid   = tid >> 5;
    const int nBase = blockIdx.x * TN;
    const bool rowOK = (nBase + tid) < nTotal;

    const uint32_t sbase = smem_u32(smemc);
    const int rowBase = wid * 32;
    const int lsw = lane & 7, l15 = lane & 15, l16 = lane >> 4;
    const int rsw = tid & 7;

    // preload all 9 neighbor ids
    int nb[KTAPS];
#pragma unroll
    for (int k = 0; k < KTAPS; ++k)
        nb[k] = rowOK ? nbr[(size_t)(nBase + tid) * KTAPS + k] : nTotal;

    // validity tile + bias tiles (static smem; visible after first barrier)
    if (HAS_BIAS) {
        uint32_t p[8];
#pragma unroll
        for (int i = 0; i < 8; ++i) {
            const uint32_t lo = (2 * i     < KTAPS && nb[2 * i]     < nTotal) ? 0x3F80u : 0u;
            const uint32_t hi = (2 * i + 1 < KTAPS && nb[2 * i + 1] < nTotal) ? 0x3F80u : 0u;
            p[i] = lo | (hi << 16);
        }
        sAV[tid][0] = make_uint4(p[0], p[1], p[2], p[3]);
        sAV[tid][1] = make_uint4(p[4], p[5], p[6], p[7]);
        sBBh[tid] = ((const uint4*)(g_biasHi + wtIdx * 1024))[tid];
        sBBl[tid] = ((const uint4*)(g_biasLo + wtIdx * 1024))[tid];
    }

    float C[2][8][4];
#pragma unroll
    for (int mt = 0; mt < 2; ++mt)
#pragma unroll
        for (int nt = 0; nt < 8; ++nt)
#pragma unroll
            for (int i = 0; i < 4; ++i) C[mt][nt][i] = 0.f;

    const __nv_bfloat16* wHiT = g_wHi + (size_t)(wtIdx * KTAPS) * 4096;
    const __nv_bfloat16* wLoT = g_wLo + (size_t)(wtIdx * KTAPS) * 4096;

    // ---- async prefetch of one tap into stage s ----
    auto prefetch = [&](int k, int s) {
        const uint4* arow = (const uint4*)(src + (size_t)nb[k] * 128);
        const uint32_t ab = sbase + s * STAGE_BYTES;
        const uint32_t aHiD = ab + tid * 128;
        const uint32_t aLoD = ab + OFF_ALO + tid * 128;
#pragma unroll
        for (int g = 0; g < 8; ++g) {
            const uint32_t off = (uint32_t)((g ^ rsw) << 4);
            cpa16(aHiD + off, arow + g);
            cpa16(aLoD + off, arow + 8 + g);
        }
        const __nv_bfloat16* bh = wHiT + (size_t)k * 4096;
        const __nv_bfloat16* bl = wLoT + (size_t)k * 4096;
#pragma unroll
        for (int i = 0; i < 4; ++i) {
            const int id = tid * 4 + i;          // 0..511 16B chunks
            const int n = id >> 3, kg = id & 7;
            const int so = n * 64 + kg * 8;
            const uint32_t dofs = (uint32_t)(n * 128 + ((kg ^ (n & 7)) << 4));
            cpa16(ab + OFF_BHI + dofs, bh + so);
            cpa16(ab + OFF_BLO + dofs, bl + so);
        }
        asm volatile("cp.async.commit_group;" ::: "memory");
    };

    prefetch(0, 0);

    for (int k = 0; k < KTAPS; ++k) {
        if (k < KTAPS - 1) {
            prefetch(k + 1, (k + 1) & 1);
            asm volatile("cp.async.wait_group 1;" ::: "memory");
        } else {
            asm volatile("cp.async.wait_group 0;" ::: "memory");
        }
        __syncthreads();

        const uint32_t ab = sbase + (k & 1) * STAGE_BYTES;
#pragma unroll
        for (int q = 0; q < 4; ++q) {
            const int kg = 2 * q + l16;
            uint32_t ah[2][4], al[2][4];
#pragma unroll
            for (int mt = 0; mt < 2; ++mt) {
                const uint32_t off =
                    (uint32_t)((rowBase + mt * 16 + l15) * 128 + ((kg ^ lsw) << 4));
                ldsm4(ah[mt], ab + off);
                ldsm4(al[mt], ab + OFF_ALO + off);
            }
            uint32_t bh[8][2], bl[8][2];
#pragma unroll
            for (int p = 0; p < 4; ++p) {
                const uint32_t off =
                    (uint32_t)((16 * p + l15) * 128 + ((kg ^ lsw) << 4));
                uint32_t r[4];
                ldsm4(r, ab + OFF_BHI + off);
                bh[2*p][0] = r[0]; bh[2*p+1][0] = r[1];
                bh[2*p][1] = r[2]; bh[2*p+1][1] = r[3];
                ldsm4(r, ab + OFF_BLO + off);
                bl[2*p][0] = r[0]; bl[2*p+1][0] = r[1];
                bl[2*p][1] = r[2]; bl[2*p+1][1] = r[3];
            }
#pragma unroll
            for (int mt = 0; mt < 2; ++mt)
#pragma unroll
                for (int nt = 0; nt < 8; ++nt) {
                    mma16816(C[mt][nt], ah[mt], bh[nt]);
                    mma16816(C[mt][nt], ah[mt], bl[nt]);
                    mma16816(C[mt][nt], al[mt], bh[nt]);
                }
        }
        if (k < KTAPS - 1) __syncthreads();   // protect stage k&1 before overwrite
    }

    // ---- bias MMA: C += V(128x16) * B(16x64), 2 terms (hi+lo) ----
    if (HAS_BIAS) {
        const uint32_t avb = smem_u32(sAV);
        const uint32_t bhb = smem_u32(sBBh);
        const uint32_t blb = smem_u32(sBBl);
        uint32_t av[2][4];
#pragma unroll
        for (int mt = 0; mt < 2; ++mt)
            ldsm4(av[mt], avb + (uint32_t)((rowBase + mt * 16 + l15) * 32 + l16 * 16));
        uint32_t bbh[8][2], bbl[8][2];
#pragma unroll
        for (int p = 0; p < 4; ++p) {
            const uint32_t off = (uint32_t)((16 * p + l15) * 32 + l16 * 16);
            uint32_t r[4];
            ldsm4(r, bhb + off);
            bbh[2*p][0] = r[0]; bbh[2*p+1][0] = r[1];
            bbh[2*p][1] = r[2]; bbh[2*p+1][1] = r[3];
            ldsm4(r, blb + off);
            bbl[2*p][0] = r[0]; bbl[2*p+1][0] = r[1];
            bbl[2*p][1] = r[2]; bbl[2*p+1][1] = r[3];
        }
#pragma unroll
        for (int mt = 0; mt < 2; ++mt)
#pragma unroll
            for (int nt = 0; nt < 8; ++nt) {
                mma16816(C[mt][nt], av[mt], bbh[nt]);
                mma16816(C[mt][nt], av[mt], bbl[nt]);
            }
    }

    // ---- epilogue: leaky on frags -> smem fp32 tile -> store + stats ----
    __syncthreads();
    float* sC = (float*)smemc;                   // [128][SC_STRIDE] (34.8KB <= stage0)
    const int fg = lane >> 2, ft2 = (lane & 3) * 2;
#pragma unroll
    for (int mt = 0; mt < 2; ++mt)
#pragma unroll
        for (int nt = 0; nt < 8; ++nt) {
            float* c = C[mt][nt];
#pragma unroll
            for (int i = 0; i < 4; ++i)
                c[i] = (c[i] > 0.f) ? c[i] : LEAK * c[i];
            const int r0 = rowBase + mt * 16 + fg;
            const int col = nt * 8 + ft2;
            *(float2*)&sC[r0 * SC_STRIDE + col]       = make_float2(c[0], c[1]);
            *(float2*)&sC[(r0 + 8) * SC_STRIDE + col] = make_float2(c[2], c[3]);
        }
    __syncthreads();

    if (rowOK) {
        const float4* rowp = (const float4*)(sC + tid * SC_STRIDE);
        if (OUT_PLANES) {
            uint4* d = (uint4*)(dstP + (size_t)(nBase + tid) * 128);
#pragma unroll
            for (int g = 0; g < 8; ++g) {
                const float4 v0 = rowp[2 * g], v1 = rowp[2 * g + 1];
                const float vv[8] = {v0.x, v0.y, v0.z, v0.w, v1.x, v1.y, v1.z, v1.w};
                uint16_t hh[8], ll[8];
#pragma unroll
                for (int e = 0; e < 8; ++e) bsplit(vv[e], hh[e], ll[e]);
                uint4 H, L;
                H.x = (uint32_t)hh[0] | ((uint32_t)hh[1] << 16);
                H.y = (uint32_t)hh[2] | ((uint32_t)hh[3] << 16);
                H.z = (uint32_t)hh[4] | ((uint32_t)hh[5] << 16);
                H.w = (uint32_t)hh[6] | ((uint32_t)hh[7] << 16);
                L.x = (uint32_t)ll[0] | ((uint32_t)ll[1] << 16);
                L.y = (uint32_t)ll[2] | ((uint32_t)ll[3] << 16);
                L.z = (uint32_t)ll[4] | ((uint32_t)ll[5] << 16);
                L.w = (uint32_t)ll[6] | ((uint32_t)ll[7] << 16);
                d[g] = H;
                d[8 + g] = L;
            }
        } else {
            float4* drow = (float4*)(dstF + (size_t)(nBase + tid) * CCH);
#pragma unroll
            for (int c4 = 0; c4 < 16; ++c4) drow[c4] = rowp[c4];
        }
    }

    {
        const int ch = tid >> 1, half = tid & 1;
        float s = 0.f, s2 = 0.f;
#pragma unroll 8
        for (int i = 0; i < 64; ++i) {
            const float v = sC[(half * 64 + i) * SC_STRIDE + ch];
            s += v; s2 += v * v;
        }
        s  += __shfl_xor_sync(0xffffffffu, s, 1);
        s2 += __shfl_xor_sync(0xffffffffu, s2, 1);
        if (!half) {
            atomicAdd(&g_sums[stage][ch], s);
            atomicAdd(&g_sumsq[stage][ch], s2);
        }
    }
}

// out = BN3(out) + BN1(y2); coefficients for stages 1,3 computed inline
__global__ __launch_bounds__(256)
void final_k(float* __restrict__ out, const float* __restrict__ y2,
             const float* __restrict__ g1_, const float* __restrict__ b1_,
             const float* __restrict__ g3_, const float* __restrict__ b3_,
             float invN, int total4)
{
    __shared__ float c1[64], s1[64], c3[64], s3[64];
    const int tid = threadIdx.x;
    if (tid < 64) {
        const float m1 = g_sums[1][tid] * invN;
        const float v1 = g_sumsq[1][tid] * invN - m1 * m1;
        const float a1 = g1_[tid] * rsqrtf(v1 + EPS_BN);
        c1[tid] = a1; s1[tid] = b1_[tid] - m1 * a1;
        const float m3 = g_sums[3][tid] * invN;
        const float v3 = g_sumsq[3][tid] * invN - m3 * m3;
        const float a3 = g3_[tid] * rsqrtf(v3 + EPS_BN);
        c3[tid] = a3; s3[tid] = b3_[tid] - m3 * a3;
    }
    __syncthreads();
    const int i = blockIdx.x * 256 + tid;
    if (i >= total4) return;
    float4 a = ((float4*)out)[i];
    const float4 b = ((const float4*)y2)[i];
    const int c = (i * 4) & 63;
    a.x = fmaf(a.x, c3[c + 0], s3[c + 0]) + fmaf(b.x, c1[c + 0], s1[c + 0]);
    a.y = fmaf(a.y, c3[c + 1], s3[c + 1]) + fmaf(b.y, c1[c + 1], s1[c + 1]);
    a.z = fmaf(a.z, c3[c + 2], s3[c + 2]) + fmaf(b.z, c1[c + 2], s1[c + 2]);
    a.w = fmaf(a.w, c3[c + 3], s3[c + 3]) + fmaf(b.w, c1[c + 3], s1[c + 3]);
    ((float4*)out)[i] = a;
}

// ---------------- launcher ----------------
extern "C" void kernel_launch(void* const* d_in, const int* in_sizes, int n_in,
                              void* d_out, int out_size)
{
    const float* features = (const float*)d_in[0];
    const float* w1   = (const float*)d_in[1];
    const float* w1_2 = (const float*)d_in[2];
    const float* w2   = (const float*)d_in[3];
    const float* w3   = (const float*)d_in[4];
    const float* g0   = (const float*)d_in[5];
    const float* b0   = (const float*)d_in[6];
    const float* g0_2 = (const float*)d_in[7];
    const float* b0_2 = (const float*)d_in[8];
    const float* g1   = (const float*)d_in[9];
    const float* b1   = (const float*)d_in[10];
    const float* g2   = (const float*)d_in[11];
    const float* b2   = (const float*)d_in[12];
    const int*   nbr13 = (const int*)d_in[13];
    const int*   nbr31 = (const int*)d_in[14];

    const int nTotal = in_sizes[0] / CCH;
    const float invN = 1.0f / (float)nTotal;
    const int grid   = (nTotal + TN - 1) / TN;
    const int gridS  = (nTotal + 255) / 256;

    cudaFuncSetAttribute(conv_mma_k<false, true>,
                         cudaFuncAttributeMaxDynamicSharedMemorySize, DSM_BYTES);
    cudaFuncSetAttribute(conv_mma_k<true, false>,
                         cudaFuncAttributeMaxDynamicSharedMemorySize, DSM_BYTES);

    float* bufB = nullptr;
    __nv_bfloat16 *fS = nullptr, *aS = nullptr;
    cudaGetSymbolAddress((void**)&bufB, g_bufB);
    cudaGetSymbolAddress((void**)&fS, g_fS);
    cudaGetSymbolAddress((void**)&aS, g_aS);
    float* out = (float*)d_out;

    zero_stats_k<<<1, 512>>>(nTotal);
    prep_plain_k<<<2 * KTAPS, 256>>>(w1, w2);
    split_k<<<gridS, 256>>>(features, fS, nTotal);

    // shortcut: conv(nbr13,w1)[planes,stats0] -> fold BN0 into w1_2 -> conv(nbr31)[fp32,stats1]
    conv_mma_k<false, true ><<<grid, NTHR, DSM_BYTES>>>(fS, nbr13, 0, nullptr, aS, nTotal, 0);
    prep_fold_k<<<KTAPS, 256>>>(w1_2, 1, 0, g0, b0, invN);
    conv_mma_k<true , false><<<grid, NTHR, DSM_BYTES>>>(aS, nbr31, 1, bufB, nullptr, nTotal, 1);

    // main: conv(nbr31,w2)[planes,stats2] -> fold BN2 into w3 -> conv(nbr13)[fp32,stats3]
    conv_mma_k<false, true ><<<grid, NTHR, DSM_BYTES>>>(fS, nbr31, 2, nullptr, aS, nTotal, 2);
    prep_fold_k<<<KTAPS, 256>>>(w3, 3, 2, g1, b1, invN);
    conv_mma_k<true , false><<<grid, NTHR, DSM_BYTES>>>(aS, nbr13, 3, out, nullptr, nTotal, 3);

    // out = BN3(out) + BN1(bufB)
    const int total4 = nTotal * CCH / 4;
    final_k<<<(total4 + 255) / 256, 256>>>(out, bufB, g0_2, b0_2, g2, b2, invN, total4);
}

// round 7
// speedup vs baseline: 34.6919x; 34.6919x over previous
#include <cuda_runtime.h>
#include <cuda_bf16.h>
#include <cstdint>

// ---------------- problem constants ----------------
#define NMAX   200000
#define CCH    64
#define KTAPS  9
#define TN     128          // rows per block (MMA M)
#define NTHR   128
#define LEAK   0.01f
#define EPS_BN 1e-5f

// per-stage dynamic smem: Ahi 16K | Alo 16K | Bhi 8K | Blo 8K = 48K, double-buffered
#define OFF_ALO 16384
#define OFF_BHI 32768
#define OFF_BLO 40960
#define STAGE_BYTES 49152
#define DSM_BYTES (2 * STAGE_BYTES)
#define SC_STRIDE 68        // epilogue fp32 tile stride (floats)

// ---------------- scratch (no cudaMalloc allowed) ----------------
__device__ float g_bufB[(size_t)NMAX * CCH];
// interleaved split planes: [row][hi 64 bf16 | lo 64 bf16]; row nTotal = zero pad
__device__ __nv_bfloat16 g_fS[((size_t)NMAX + 1) * 128];
__device__ __nv_bfloat16 g_aS[((size_t)NMAX + 1) * 128];
__device__ __nv_bfloat16 g_wHi[4 * KTAPS * 64 * 64];  // [tensor][tap][o][c]
__device__ __nv_bfloat16 g_wLo[4 * KTAPS * 64 * 64];
__device__ __nv_bfloat16 g_biasHi[4 * 64 * 16];       // [tensor][o*16 + tap]
__device__ __nv_bfloat16 g_biasLo[4 * 64 * 16];
__device__ float g_sums [4][CCH];
__device__ float g_sumsq[4][CCH];

// ---------------- helpers ----------------
__device__ __forceinline__ uint32_t smem_u32(const void* p) {
    uint32_t a;
    asm("{ .reg .u64 t; cvta.to.shared.u64 t, %1; cvt.u32.u64 %0, t; }" : "=r"(a) : "l"(p));
    return a;
}
__device__ __forceinline__ void ldsm4(uint32_t* r, uint32_t addr) {
    asm volatile("ldmatrix.sync.aligned.m8n8.x4.shared.b16 {%0,%1,%2,%3}, [%4];"
        : "=r"(r[0]), "=r"(r[1]), "=r"(r[2]), "=r"(r[3]) : "r"(addr));
}
__device__ __forceinline__ void mma16816(float* c, const uint32_t* a, const uint32_t* b) {
    asm volatile("mma.sync.aligned.m16n8k16.row.col.f32.bf16.bf16.f32 "
        "{%0,%1,%2,%3}, {%4,%5,%6,%7}, {%8,%9}, {%0,%1,%2,%3};"
        : "+f"(c[0]), "+f"(c[1]), "+f"(c[2]), "+f"(c[3])
        : "r"(a[0]), "r"(a[1]), "r"(a[2]), "r"(a[3]), "r"(b[0]), "r"(b[1]));
}
__device__ __forceinline__ void bsplit(float v, uint16_t &h, uint16_t &l) {
    __nv_bfloat16 bh = __float2bfloat16(v);
    h = __bfloat16_as_ushort(bh);
    l = __bfloat16_as_ushort(__float2bfloat16(v - __bfloat162float(bh)));
}

// ---------------- aux kernels ----------------
__global__ void zero_stats_k(int nTotal) {
    const int i = threadIdx.x;   // 512
    if (i < 256) ((float*)g_sums)[i] = 0.f;
    else ((float*)g_sumsq)[i - 256] = 0.f;
#pragma unroll
    for (int j = 0; j < 4; ++j) {
        ((uint32_t*)g_biasHi)[i + j * 512] = 0u;
        ((uint32_t*)g_biasLo)[i + j * 512] = 0u;
    }
    if (i < 64)  ((uint32_t*)(g_fS + (size_t)nTotal * 128))[i] = 0u;
    else if (i < 128) ((uint32_t*)(g_aS + (size_t)nTotal * 128))[i - 64] = 0u;
}

// plain weights [9][c][o] -> planes [tensor][tap][o][c] (tensors 0 and 2)
__global__ void prep_plain_k(const float* __restrict__ w1, const float* __restrict__ w2) {
    const int t = (blockIdx.x < KTAPS) ? 0 : 2;
    const int k = blockIdx.x % KTAPS;
    const float* src = ((t == 0) ? w1 : w2) + k * 4096;
    __nv_bfloat16* dh = g_wHi + (size_t)(t * KTAPS + k) * 4096;
    __nv_bfloat16* dl = g_wLo + (size_t)(t * KTAPS + k) * 4096;
#pragma unroll
    for (int i = 0; i < 16; ++i) {
        const int j = threadIdx.x + i * 256;     // j = c*64 + o
        const int c = j >> 6, o = j & 63;
        uint16_t h, l;
        bsplit(src[j], h, l);
        dh[o * 64 + c] = __ushort_as_bfloat16(h);
        dl[o * 64 + c] = __ushort_as_bfloat16(l);
    }
}

// fold BN(stage) of the INPUT into weights: W' = scale[c]*W, bias_k[o] = sum_c shift[c]*W[c,o]
__global__ void prep_fold_k(const float* __restrict__ w, int tensor, int stage,
                            const float* __restrict__ gamma,
                            const float* __restrict__ beta, float invN) {
    __shared__ float sc[64], sh[64];
    const int k = blockIdx.x, tid = threadIdx.x;
    if (tid < 64) {
        const float m = g_sums[stage][tid] * invN;
        const float v = g_sumsq[stage][tid] * invN - m * m;
        const float a = gamma[tid] * rsqrtf(v + EPS_BN);
        sc[tid] = a;
        sh[tid] = beta[tid] - m * a;
    }
    __syncthreads();
    const float* src = w + (size_t)k * 4096;
    __nv_bfloat16* dh = g_wHi + (size_t)(tensor * KTAPS + k) * 4096;
    __nv_bfloat16* dl = g_wLo + (size_t)(tensor * KTAPS + k) * 4096;
#pragma unroll
    for (int i = 0; i < 16; ++i) {
        const int j = tid + i * 256;             // j = c*64 + o
        const int c = j >> 6, o = j & 63;
        uint16_t h, l;
        bsplit(sc[c] * src[j], h, l);
        dh[o * 64 + c] = __ushort_as_bfloat16(h);
        dl[o * 64 + c] = __ushort_as_bfloat16(l);
    }
    if (tid < 64) {
        float s = 0.f;
#pragma unroll 8
        for (int c = 0; c < 64; ++c) s += sh[c] * src[c * 64 + tid];
        uint16_t h, l;
        bsplit(s, h, l);
        g_biasHi[tensor * 1024 + tid * 16 + k] = __ushort_as_bfloat16(h);
        g_biasLo[tensor * 1024 + tid * 16 + k] = __ushort_as_bfloat16(l);
    }
}

// fp32 features -> interleaved bf16 hi/lo planes (once)
__global__ __launch_bounds__(256)
void split_k(const float* __restrict__ src, __nv_bfloat16* __restrict__ dst, int nTotal) {
    const int row = blockIdx.x * 256 + threadIdx.x;
    if (row >= nTotal) return;
    const float4* s = (const float4*)(src + (size_t)row * CCH);
    uint4* d = (uint4*)(dst + (size_t)row * 128);
#pragma unroll
    for (int g = 0; g < 8; ++g) {
        const float4 v0 = s[2 * g], v1 = s[2 * g + 1];
        const float vv[8] = {v0.x, v0.y, v0.z, v0.w, v1.x, v1.y, v1.z, v1.w};
        uint16_t hh[8], ll[8];
#pragma unroll
        for (int e = 0; e < 8; ++e) bsplit(vv[e], hh[e], ll[e]);
        uint4 H, L;
        H.x = (uint32_t)hh[0] | ((uint32_t)hh[1] << 16);
        H.y = (uint32_t)hh[2] | ((uint32_t)hh[3] << 16);
        H.z = (uint32_t)hh[4] | ((uint32_t)hh[5] << 16);
        H.w = (uint32_t)hh[6] | ((uint32_t)hh[7] << 16);
        L.x = (uint32_t)ll[0] | ((uint32_t)ll[1] << 16);
        L.y = (uint32_t)ll[2] | ((uint32_t)ll[3] << 16);
        L.z = (uint32_t)ll[4] | ((uint32_t)ll[5] << 16);
        L.w = (uint32_t)ll[6] | ((uint32_t)ll[7] << 16);
        d[g] = H;
        d[8 + g] = L;
    }
}

// ---------------- main conv kernel (mma.sync bf16 3-term, reg-staged pipeline) ----------------
template <bool HAS_BIAS, bool OUT_PLANES>
__global__ __launch_bounds__(NTHR)
void conv_mma_k(const __nv_bfloat16* __restrict__ src,   // [N+1][128] hi|lo
                const int* __restrict__ nbr, int wtIdx,
                float* __restrict__ dstF, __nv_bfloat16* __restrict__ dstP,
                int nTotal, int stage)
{
    extern __shared__ __align__(128) char smemc[];
    __shared__ uint4 sAV[128][2];     // validity [128 rows][16 taps] bf16
    __shared__ uint4 sBBh[128];       // bias hi [64 o][16 taps] bf16
    __shared__ uint4 sBBl[128];

    const int tid   = threadIdx.x;
    const int lane  = tid & 31;
    const int wid   = tid >> 5;
    const int nBase = blockIdx.x * TN;
    const bool rowOK = (nBase + tid) < nTotal;

    const uint32_t sbase = smem_u32(smemc);
    const int rowBase = wid * 32;
    const int lsw = lane & 7, l15 = lane & 15, l16 = lane >> 4;
    const int rsw = tid & 7;

    // preload all 9 neighbor ids
    int nb[KTAPS];
#pragma unroll
    for (int k = 0; k < KTAPS; ++k)
        nb[k] = rowOK ? nbr[(size_t)(nBase + tid) * KTAPS + k] : nTotal;

    if (HAS_BIAS) {
        uint32_t p[8];
#pragma unroll
        for (int i = 0; i < 8; ++i) {
            const uint32_t lo = (2 * i     < KTAPS && nb[2 * i]     < nTotal) ? 0x3F80u : 0u;
            const uint32_t hi = (2 * i + 1 < KTAPS && nb[2 * i + 1] < nTotal) ? 0x3F80u : 0u;
            p[i] = lo | (hi << 16);
        }
        sAV[tid][0] = make_uint4(p[0], p[1], p[2], p[3]);
        sAV[tid][1] = make_uint4(p[4], p[5], p[6], p[7]);
        sBBh[tid] = ((const uint4*)(g_biasHi + wtIdx * 1024))[tid];
        sBBl[tid] = ((const uint4*)(g_biasLo + wtIdx * 1024))[tid];
    }

    float C[2][8][4];
#pragma unroll
    for (int mt = 0; mt < 2; ++mt)
#pragma unroll
        for (int nt = 0; nt < 8; ++nt)
#pragma unroll
            for (int i = 0; i < 4; ++i) C[mt][nt][i] = 0.f;

    const __nv_bfloat16* wHiT = g_wHi + (size_t)(wtIdx * KTAPS) * 4096;
    const __nv_bfloat16* wLoT = g_wLo + (size_t)(wtIdx * KTAPS) * 4096;

    // ---- register staging ----
    uint4 pa[16];   // A row: hi[0..7], lo[8..15]
    uint4 pb[8];    // B chunks: hi[0..3], lo[4..7]

    auto ldgTap = [&](int k) {
        const uint4* arow = (const uint4*)(src + (size_t)nb[k] * 128);
#pragma unroll
        for (int g = 0; g < 16; ++g) pa[g] = arow[g];
        const uint4* bh = (const uint4*)(wHiT + (size_t)k * 4096);
        const uint4* bl = (const uint4*)(wLoT + (size_t)k * 4096);
#pragma unroll
        for (int i = 0; i < 4; ++i) {
            const int id = tid * 4 + i;          // 0..511 16B chunks
            const int n = id >> 3, kg = id & 7;
            const int so = (n * 64 + kg * 8) >> 3;   // uint4 index
            pb[i]     = bh[so];
            pb[4 + i] = bl[so];
        }
    };
    auto stsTap = [&](int s) {
        char* ab = smemc + s * STAGE_BYTES;
        char* aHiRow = ab + tid * 128;
        char* aLoRow = ab + OFF_ALO + tid * 128;
#pragma unroll
        for (int g = 0; g < 8; ++g) {
            const int off = (g ^ rsw) << 4;
            *(uint4*)(aHiRow + off) = pa[g];
            *(uint4*)(aLoRow + off) = pa[8 + g];
        }
#pragma unroll
        for (int i = 0; i < 4; ++i) {
            const int id = tid * 4 + i;
            const int n = id >> 3, kg = id & 7;
            const int dofs = n * 128 + ((kg ^ (n & 7)) << 4);
            *(uint4*)(ab + OFF_BHI + dofs) = pb[i];
            *(uint4*)(ab + OFF_BLO + dofs) = pb[4 + i];
        }
    };

    ldgTap(0);
    stsTap(0);

    for (int k = 0; k < KTAPS; ++k) {
        __syncthreads();                 // stage k&1 visible; stage (k+1)&1 free

        if (k < KTAPS - 1) ldgTap(k + 1);   // LDG latency hides under MMAs below

        const uint32_t ab = sbase + (k & 1) * STAGE_BYTES;
#pragma unroll
        for (int q = 0; q < 4; ++q) {
            const int kg = 2 * q + l16;
            uint32_t ah[2][4], al[2][4];
#pragma unroll
            for (int mt = 0; mt < 2; ++mt) {
                const uint32_t off =
                    (uint32_t)((rowBase + mt * 16 + l15) * 128 + ((kg ^ lsw) << 4));
                ldsm4(ah[mt], ab + off);
                ldsm4(al[mt], ab + OFF_ALO + off);
            }
            uint32_t bh[8][2], bl[8][2];
#pragma unroll
            for (int p = 0; p < 4; ++p) {
                const uint32_t off =
                    (uint32_t)((16 * p + l15) * 128 + ((kg ^ lsw) << 4));
                uint32_t r[4];
                ldsm4(r, ab + OFF_BHI + off);
                bh[2*p][0] = r[0]; bh[2*p+1][0] = r[1];
                bh[2*p][1] = r[2]; bh[2*p+1][1] = r[3];
                ldsm4(r, ab + OFF_BLO + off);
                bl[2*p][0] = r[0]; bl[2*p+1][0] = r[1];
                bl[2*p][1] = r[2]; bl[2*p+1][1] = r[3];
            }
#pragma unroll
            for (int mt = 0; mt < 2; ++mt)
#pragma unroll
                for (int nt = 0; nt < 8; ++nt) {
                    mma16816(C[mt][nt], ah[mt], bh[nt]);
                    mma16816(C[mt][nt], ah[mt], bl[nt]);
                    mma16816(C[mt][nt], al[mt], bh[nt]);
                }
        }

        if (k < KTAPS - 1) stsTap((k + 1) & 1);
    }

    // ---- bias MMA: C += V(128x16) * B(16x64), 2 terms (hi+lo) ----
    if (HAS_BIAS) {
        const uint32_t avb = smem_u32(sAV);
        const uint32_t bhb = smem_u32(sBBh);
        const uint32_t blb = smem_u32(sBBl);
        uint32_t av[2][4];
#pragma unroll
        for (int mt = 0; mt < 2; ++mt)
            ldsm4(av[mt], avb + (uint32_t)((rowBase + mt * 16 + l15) * 32 + l16 * 16));
        uint32_t bbh[8][2], bbl[8][2];
#pragma unroll
        for (int p = 0; p < 4; ++p) {
            const uint32_t off = (uint32_t)((16 * p + l15) * 32 + l16 * 16);
            uint32_t r[4];
            ldsm4(r, bhb + off);
            bbh[2*p][0] = r[0]; bbh[2*p+1][0] = r[1];
            bbh[2*p][1] = r[2]; bbh[2*p+1][1] = r[3];
            ldsm4(r, blb + off);
            bbl[2*p][0] = r[0]; bbl[2*p+1][0] = r[1];
            bbl[2*p][1] = r[2]; bbl[2*p+1][1] = r[3];
        }
#pragma unroll
        for (int mt = 0; mt < 2; ++mt)
#pragma unroll
            for (int nt = 0; nt < 8; ++nt) {
                mma16816(C[mt][nt], av[mt], bbh[nt]);
                mma16816(C[mt][nt], av[mt], bbl[nt]);
            }
    }

    // ---- epilogue: leaky on frags -> smem fp32 tile -> store + stats ----
    __syncthreads();
    float* sC = (float*)smemc;                   // [128][SC_STRIDE] (34.8KB <= stage0)
    const int fg = lane >> 2, ft2 = (lane & 3) * 2;
#pragma unroll
    for (int mt = 0; mt < 2; ++mt)
#pragma unroll
        for (int nt = 0; nt < 8; ++nt) {
            float* c = C[mt][nt];
#pragma unroll
            for (int i = 0; i < 4; ++i)
                c[i] = (c[i] > 0.f) ? c[i] : LEAK * c[i];
            const int r0 = rowBase + mt * 16 + fg;
            const int col = nt * 8 + ft2;
            *(float2*)&sC[r0 * SC_STRIDE + col]       = make_float2(c[0], c[1]);
            *(float2*)&sC[(r0 + 8) * SC_STRIDE + col] = make_float2(c[2], c[3]);
        }
    __syncthreads();

    if (rowOK) {
        const float4* rowp = (const float4*)(sC + tid * SC_STRIDE);
        if (OUT_PLANES) {
            uint4* d = (uint4*)(dstP + (size_t)(nBase + tid) * 128);
#pragma unroll
            for (int g = 0; g < 8; ++g) {
                const float4 v0 = rowp[2 * g], v1 = rowp[2 * g + 1];
                const float vv[8] = {v0.x, v0.y, v0.z, v0.w, v1.x, v1.y, v1.z, v1.w};
                uint16_t hh[8], ll[8];
#pragma unroll
                for (int e = 0; e < 8; ++e) bsplit(vv[e], hh[e], ll[e]);
                uint4 H, L;
                H.x = (uint32_t)hh[0] | ((uint32_t)hh[1] << 16);
                H.y = (uint32_t)hh[2] | ((uint32_t)hh[3] << 16);
                H.z = (uint32_t)hh[4] | ((uint32_t)hh[5] << 16);
                H.w = (uint32_t)hh[6] | ((uint32_t)hh[7] << 16);
                L.x = (uint32_t)ll[0] | ((uint32_t)ll[1] << 16);
                L.y = (uint32_t)ll[2] | ((uint32_t)ll[3] << 16);
                L.z = (uint32_t)ll[4] | ((uint32_t)ll[5] << 16);
                L.w = (uint32_t)ll[6] | ((uint32_t)ll[7] << 16);
                d[g] = H;
                d[8 + g] = L;
            }
        } else {
            float4* drow = (float4*)(dstF + (size_t)(nBase + tid) * CCH);
#pragma unroll
            for (int c4 = 0; c4 < 16; ++c4) drow[c4] = rowp[c4];
        }
    }

    {
        const int ch = tid >> 1, half = tid & 1;
        float s = 0.f, s2 = 0.f;
#pragma unroll 8
        for (int i = 0; i < 64; ++i) {
            const float v = sC[(half * 64 + i) * SC_STRIDE + ch];
            s += v; s2 += v * v;
        }
        s  += __shfl_xor_sync(0xffffffffu, s, 1);
        s2 += __shfl_xor_sync(0xffffffffu, s2, 1);
        if (!half) {
            atomicAdd(&g_sums[stage][ch], s);
            atomicAdd(&g_sumsq[stage][ch], s2);
        }
    }
}

// out = BN3(out) + BN1(y2); coefficients for stages 1,3 computed inline
__global__ __launch_bounds__(256)
void final_k(float* __restrict__ out, const float* __restrict__ y2,
             const float* __restrict__ g1_, const float* __restrict__ b1_,
             const float* __restrict__ g3_, const float* __restrict__ b3_,
             float invN, int total4)
{
    __shared__ float c1[64], s1[64], c3[64], s3[64];
    const int tid = threadIdx.x;
    if (tid < 64) {
        const float m1 = g_sums[1][tid] * invN;
        const float v1 = g_sumsq[1][tid] * invN - m1 * m1;
        const float a1 = g1_[tid] * rsqrtf(v1 + EPS_BN);
        c1[tid] = a1; s1[tid] = b1_[tid] - m1 * a1;
        const float m3 = g_sums[3][tid] * invN;
        const float v3 = g_sumsq[3][tid] * invN - m3 * m3;
        const float a3 = g3_[tid] * rsqrtf(v3 + EPS_BN);
        c3[tid] = a3; s3[tid] = b3_[tid] - m3 * a3;
    }
    __syncthreads();
    const int i = blockIdx.x * 256 + tid;
    if (i >= total4) return;
    float4 a = ((float4*)out)[i];
    const float4 b = ((const float4*)y2)[i];
    const int c = (i * 4) & 63;
    a.x = fmaf(a.x, c3[c + 0], s3[c + 0]) + fmaf(b.x, c1[c + 0], s1[c + 0]);
    a.y = fmaf(a.y, c3[c + 1], s3[c + 1]) + fmaf(b.y, c1[c + 1], s1[c + 1]);
    a.z = fmaf(a.z, c3[c + 2], s3[c + 2]) + fmaf(b.z, c1[c + 2], s1[c + 2]);
    a.w = fmaf(a.w, c3[c + 3], s3[c + 3]) + fmaf(b.w, c1[c + 3], s1[c + 3]);
    ((float4*)out)[i] = a;
}

// ---------------- launcher ----------------
extern "C" void kernel_launch(void* const* d_in, const int* in_sizes, int n_in,
                              void* d_out, int out_size)
{
    const float* features = (const float*)d_in[0];
    const float* w1   = (const float*)d_in[1];
    const float* w1_2 = (const float*)d_in[2];
    const float* w2   = (const float*)d_in[3];
    const float* w3   = (const float*)d_in[4];
    const float* g0   = (const float*)d_in[5];
    const float* b0   = (const float*)d_in[6];
    const float* g0_2 = (const float*)d_in[7];
    const float* b0_2 = (const float*)d_in[8];
    const float* g1   = (const float*)d_in[9];
    const float* b1   = (const float*)d_in[10];
    const float* g2   = (const float*)d_in[11];
    const float* b2   = (const float*)d_in[12];
    const int*   nbr13 = (const int*)d_in[13];
    const int*   nbr31 = (const int*)d_in[14];

    const int nTotal = in_sizes[0] / CCH;
    const float invN = 1.0f / (float)nTotal;
    const int grid   = (nTotal + TN - 1) / TN;
    const int gridS  = (nTotal + 255) / 256;

    cudaFuncSetAttribute(conv_mma_k<false, true>,
                         cudaFuncAttributeMaxDynamicSharedMemorySize, DSM_BYTES);
    cudaFuncSetAttribute(conv_mma_k<true, false>,
                         cudaFuncAttributeMaxDynamicSharedMemorySize, DSM_BYTES);

    float* bufB = nullptr;
    __nv_bfloat16 *fS = nullptr, *aS = nullptr;
    cudaGetSymbolAddress((void**)&bufB, g_bufB);
    cudaGetSymbolAddress((void**)&fS, g_fS);
    cudaGetSymbolAddress((void**)&aS, g_aS);
    float* out = (float*)d_out;

    zero_stats_k<<<1, 512>>>(nTotal);
    prep_plain_k<<<2 * KTAPS, 256>>>(w1, w2);
    split_k<<<gridS, 256>>>(features, fS, nTotal);

    // shortcut: conv(nbr13,w1)[planes,stats0] -> fold BN0 into w1_2 -> conv(nbr31)[fp32,stats1]
    conv_mma_k<false, true ><<<grid, NTHR, DSM_BYTES>>>(fS, nbr13, 0, nullptr, aS, nTotal, 0);
    prep_fold_k<<<KTAPS, 256>>>(w1_2, 1, 0, g0, b0, invN);
    conv_mma_k<true , false><<<grid, NTHR, DSM_BYTES>>>(aS, nbr31, 1, bufB, nullptr, nTotal, 1);

    // main: conv(nbr31,w2)[planes,stats2] -> fold BN2 into w3 -> conv(nbr13)[fp32,stats3]
    conv_mma_k<false, true ><<<grid, NTHR, DSM_BYTES>>>(fS, nbr31, 2, nullptr, aS, nTotal, 2);
    prep_fold_k<<<KTAPS, 256>>>(w3, 3, 2, g1, b1, invN);
    conv_mma_k<true , false><<<grid, NTHR, DSM_BYTES>>>(aS, nbr13, 3, out, nullptr, nTotal, 3);

    // out = BN3(out) + BN1(bufB)
    const int total4 = nTotal * CCH / 4;
    final_k<<<(total4 + 255) / 256, 256>>>(out, bufB, g0_2, b0_2, g2, b2, invN, total4);
}

// round 8
// speedup vs baseline: 47.1987x; 1.3605x over previous
#include <cuda_runtime.h>
#include <cuda_fp16.h>
#include <cstdint>

// ---------------- problem constants ----------------
#define NMAX   200000
#define CCH    64
#define KTAPS  9
#define TN     128          // rows per block (MMA M)
#define NTHR   128
#define LEAK   0.01f
#define EPS_BN 1e-5f
#define WSCALE 256.0f       // weight scaling (keeps fp16 lo-plane normal)
#define INV_WSCALE (1.0f / 256.0f)

// per-stage dynamic smem: A 16K | Bhi 8K | Blo 8K = 32K, double-buffered
#define OFF_BHI 16384
#define OFF_BLO 24576
#define STAGE_BYTES 32768
#define DSM_BYTES (2 * STAGE_BYTES)
#define SC_STRIDE 68        // epilogue fp32 tile stride (floats)

// ---------------- scratch (no cudaMalloc allowed) ----------------
__device__ float g_bufB[(size_t)NMAX * CCH];
// fp16 feature rows: [row][64 fp16]; row nTotal = zero pad
__device__ __half g_fS[((size_t)NMAX + 1) * 64];
__device__ __half g_aS[((size_t)NMAX + 1) * 64];
__device__ __half g_wHi[4 * KTAPS * 64 * 64];  // [tensor][tap][o][c], x256
__device__ __half g_wLo[4 * KTAPS * 64 * 64];
__device__ __half g_biasHi[4 * 64 * 16];       // [tensor][o*16 + tap], x256
__device__ __half g_biasLo[4 * 64 * 16];
__device__ float g_sums [4][CCH];
__device__ float g_sumsq[4][CCH];

// ---------------- helpers ----------------
__device__ __forceinline__ uint32_t smem_u32(const void* p) {
    uint32_t a;
    asm("{ .reg .u64 t; cvta.to.shared.u64 t, %1; cvt.u32.u64 %0, t; }" : "=r"(a) : "l"(p));
    return a;
}
__device__ __forceinline__ void ldsm4(uint32_t* r, uint32_t addr) {
    asm volatile("ldmatrix.sync.aligned.m8n8.x4.shared.b16 {%0,%1,%2,%3}, [%4];"
        : "=r"(r[0]), "=r"(r[1]), "=r"(r[2]), "=r"(r[3]) : "r"(addr));
}
__device__ __forceinline__ void mma16816(float* c, const uint32_t* a, const uint32_t* b) {
    asm volatile("mma.sync.aligned.m16n8k16.row.col.f32.f16.f16.f32 "
        "{%0,%1,%2,%3}, {%4,%5,%6,%7}, {%8,%9}, {%0,%1,%2,%3};"
        : "+f"(c[0]), "+f"(c[1]), "+f"(c[2]), "+f"(c[3])
        : "r"(a[0]), "r"(a[1]), "r"(a[2]), "r"(a[3]), "r"(b[0]), "r"(b[1]));
}
__device__ __forceinline__ void hsplit(float v, uint16_t &h, uint16_t &l) {
    __half hh = __float2half_rn(v);
    h = __half_as_ushort(hh);
    l = __half_as_ushort(__float2half_rn(v - __half2float(hh)));
}
__device__ __forceinline__ uint32_t pack2h(float a, float b) {
    __half2 h = __floats2half2_rn(a, b);
    return *(uint32_t*)&h;
}

// ---------------- aux kernels ----------------
__global__ void zero_stats_k(int nTotal) {
    const int i = threadIdx.x;   // 512
    if (i < 256) ((float*)g_sums)[i] = 0.f;
    else ((float*)g_sumsq)[i - 256] = 0.f;
#pragma unroll
    for (int j = 0; j < 4; ++j) {
        ((uint32_t*)g_biasHi)[i + j * 512] = 0u;
        ((uint32_t*)g_biasLo)[i + j * 512] = 0u;
    }
    if (i < 32) ((uint32_t*)(g_fS + (size_t)nTotal * 64))[i] = 0u;
    else if (i < 64) ((uint32_t*)(g_aS + (size_t)nTotal * 64))[i - 32] = 0u;
}

// plain weights [9][c][o] -> fp16 planes [tensor][tap][o][c] x256 (tensors 0,2)
__global__ void prep_plain_k(const float* __restrict__ w1, const float* __restrict__ w2) {
    const int t = (blockIdx.x < KTAPS) ? 0 : 2;
    const int k = blockIdx.x % KTAPS;
    const float* src = ((t == 0) ? w1 : w2) + k * 4096;
    __half* dh = g_wHi + (size_t)(t * KTAPS + k) * 4096;
    __half* dl = g_wLo + (size_t)(t * KTAPS + k) * 4096;
#pragma unroll
    for (int i = 0; i < 16; ++i) {
        const int j = threadIdx.x + i * 256;     // j = c*64 + o
        const int c = j >> 6, o = j & 63;
        uint16_t h, l;
        hsplit(src[j] * WSCALE, h, l);
        dh[o * 64 + c] = __ushort_as_half(h);
        dl[o * 64 + c] = __ushort_as_half(l);
    }
}

// fold BN(stage) into weights: W' = 256*scale[c]*W; bias_k[o] = 256*sum_c shift[c]*W[c,o]
__global__ void prep_fold_k(const float* __restrict__ w, int tensor, int stage,
                            const float* __restrict__ gamma,
                            const float* __restrict__ beta, float invN) {
    __shared__ float sc[64], sh[64];
    const int k = blockIdx.x, tid = threadIdx.x;
    if (tid < 64) {
        const float m = g_sums[stage][tid] * invN;
        const float v = g_sumsq[stage][tid] * invN - m * m;
        const float a = gamma[tid] * rsqrtf(v + EPS_BN);
        sc[tid] = a;
        sh[tid] = beta[tid] - m * a;
    }
    __syncthreads();
    const float* src = w + (size_t)k * 4096;
    __half* dh = g_wHi + (size_t)(tensor * KTAPS + k) * 4096;
    __half* dl = g_wLo + (size_t)(tensor * KTAPS + k) * 4096;
#pragma unroll
    for (int i = 0; i < 16; ++i) {
        const int j = tid + i * 256;             // j = c*64 + o
        const int c = j >> 6, o = j & 63;
        uint16_t h, l;
        hsplit(sc[c] * src[j] * WSCALE, h, l);
        dh[o * 64 + c] = __ushort_as_half(h);
        dl[o * 64 + c] = __ushort_as_half(l);
    }
    if (tid < 64) {
        float s = 0.f;
#pragma unroll 8
        for (int c = 0; c < 64; ++c) s += sh[c] * src[c * 64 + tid];
        uint16_t h, l;
        hsplit(s * WSCALE, h, l);
        g_biasHi[tensor * 1024 + tid * 16 + k] = __ushort_as_half(h);
        g_biasLo[tensor * 1024 + tid * 16 + k] = __ushort_as_half(l);
    }
}

// fp32 features -> fp16 rows (once)
__global__ __launch_bounds__(256)
void split_k(const float* __restrict__ src, __half* __restrict__ dst, int nTotal) {
    const int row = blockIdx.x * 256 + threadIdx.x;
    if (row >= nTotal) return;
    const float4* s = (const float4*)(src + (size_t)row * CCH);
    uint4* d = (uint4*)(dst + (size_t)row * 64);
#pragma unroll
    for (int g = 0; g < 8; ++g) {
        const float4 v0 = s[2 * g], v1 = s[2 * g + 1];
        uint4 o;
        o.x = pack2h(v0.x, v0.y);
        o.y = pack2h(v0.z, v0.w);
        o.z = pack2h(v1.x, v1.y);
        o.w = pack2h(v1.z, v1.w);
        d[g] = o;
    }
}

// ---------------- main conv kernel (mma.sync fp16 2-term, reg-staged pipeline) ----------------
template <bool HAS_BIAS, bool OUT_PLANES>
__global__ __launch_bounds__(NTHR)
void conv_mma_k(const __half* __restrict__ src,   // [N+1][64] fp16
                const int* __restrict__ nbr, int wtIdx,
                float* __restrict__ dstF, __half* __restrict__ dstP,
                int nTotal, int stage)
{
    extern __shared__ __align__(128) char smemc[];
    __shared__ uint4 sAV[128][2];     // validity [128 rows][16 taps] fp16
    __shared__ uint4 sBBh[128];       // bias hi [64 o][16 taps] fp16
    __shared__ uint4 sBBl[128];

    const int tid   = threadIdx.x;
    const int lane  = tid & 31;
    const int wid   = tid >> 5;
    const int nBase = blockIdx.x * TN;
    const bool rowOK = (nBase + tid) < nTotal;

    const uint32_t sbase = smem_u32(smemc);
    const int rowBase = wid * 32;
    const int lsw = lane & 7, l15 = lane & 15, l16 = lane >> 4;
    const int rsw = tid & 7;

    // preload all 9 neighbor ids
    int nb[KTAPS];
#pragma unroll
    for (int k = 0; k < KTAPS; ++k)
        nb[k] = rowOK ? nbr[(size_t)(nBase + tid) * KTAPS + k] : nTotal;

    if (HAS_BIAS) {
        const uint32_t one = 0x3C00u;   // fp16 1.0
        uint32_t p[8];
#pragma unroll
        for (int i = 0; i < 8; ++i) {
            const uint32_t lo = (2 * i     < KTAPS && nb[2 * i]     < nTotal) ? one : 0u;
            const uint32_t hi = (2 * i + 1 < KTAPS && nb[2 * i + 1] < nTotal) ? one : 0u;
            p[i] = lo | (hi << 16);
        }
        sAV[tid][0] = make_uint4(p[0], p[1], p[2], p[3]);
        sAV[tid][1] = make_uint4(p[4], p[5], p[6], p[7]);
        sBBh[tid] = ((const uint4*)(g_biasHi + wtIdx * 1024))[tid];
        sBBl[tid] = ((const uint4*)(g_biasLo + wtIdx * 1024))[tid];
    }

    float C[2][8][4];
#pragma unroll
    for (int mt = 0; mt < 2; ++mt)
#pragma unroll
        for (int nt = 0; nt < 8; ++nt)
#pragma unroll
            for (int i = 0; i < 4; ++i) C[mt][nt][i] = 0.f;

    const __half* wHiT = g_wHi + (size_t)(wtIdx * KTAPS) * 4096;
    const __half* wLoT = g_wLo + (size_t)(wtIdx * KTAPS) * 4096;

    // ---- register staging ----
    uint4 pa[8];    // A row (single fp16 plane, 128B)
    uint4 pb[8];    // B chunks: hi[0..3], lo[4..7]

    auto ldgTap = [&](int k) {
        const uint4* arow = (const uint4*)(src + (size_t)nb[k] * 64);
#pragma unroll
        for (int g = 0; g < 8; ++g) pa[g] = arow[g];
        const uint4* bh = (const uint4*)(wHiT + (size_t)k * 4096);
        const uint4* bl = (const uint4*)(wLoT + (size_t)k * 4096);
#pragma unroll
        for (int i = 0; i < 4; ++i) {
            const int id = tid * 4 + i;          // 0..511 16B chunks
            const int n = id >> 3, kg = id & 7;
            const int so = (n * 64 + kg * 8) >> 3;   // uint4 index
            pb[i]     = bh[so];
            pb[4 + i] = bl[so];
        }
    };
    auto stsTap = [&](int s) {
        char* ab = smemc + s * STAGE_BYTES;
        char* aRow = ab + tid * 128;
#pragma unroll
        for (int g = 0; g < 8; ++g) {
            const int off = (g ^ rsw) << 4;
            *(uint4*)(aRow + off) = pa[g];
        }
#pragma unroll
        for (int i = 0; i < 4; ++i) {
            const int id = tid * 4 + i;
            const int n = id >> 3, kg = id & 7;
            const int dofs = n * 128 + ((kg ^ (n & 7)) << 4);
            *(uint4*)(ab + OFF_BHI + dofs) = pb[i];
            *(uint4*)(ab + OFF_BLO + dofs) = pb[4 + i];
        }
    };

    ldgTap(0);
    stsTap(0);

    for (int k = 0; k < KTAPS; ++k) {
        __syncthreads();                 // stage k&1 visible; stage (k+1)&1 free

        if (k < KTAPS - 1) ldgTap(k + 1);   // LDG latency hides under MMAs below

        const uint32_t ab = sbase + (k & 1) * STAGE_BYTES;
#pragma unroll
        for (int q = 0; q < 4; ++q) {
            const int kg = 2 * q + l16;
            uint32_t a_[2][4];
#pragma unroll
            for (int mt = 0; mt < 2; ++mt) {
                const uint32_t off =
                    (uint32_t)((rowBase + mt * 16 + l15) * 128 + ((kg ^ lsw) << 4));
                ldsm4(a_[mt], ab + off);
            }
            uint32_t bh[8][2], bl[8][2];
#pragma unroll
            for (int p = 0; p < 4; ++p) {
                const uint32_t off =
                    (uint32_t)((16 * p + l15) * 128 + ((kg ^ lsw) << 4));
                uint32_t r[4];
                ldsm4(r, ab + OFF_BHI + off);
                bh[2*p][0] = r[0]; bh[2*p+1][0] = r[1];
                bh[2*p][1] = r[2]; bh[2*p+1][1] = r[3];
                ldsm4(r, ab + OFF_BLO + off);
                bl[2*p][0] = r[0]; bl[2*p+1][0] = r[1];
                bl[2*p][1] = r[2]; bl[2*p+1][1] = r[3];
            }
#pragma unroll
            for (int mt = 0; mt < 2; ++mt)
#pragma unroll
                for (int nt = 0; nt < 8; ++nt) {
                    mma16816(C[mt][nt], a_[mt], bh[nt]);
                    mma16816(C[mt][nt], a_[mt], bl[nt]);
                }
        }

        if (k < KTAPS - 1) stsTap((k + 1) & 1);
    }

    // ---- bias MMA: C += V(128x16) * B(16x64), hi + lo ----
    if (HAS_BIAS) {
        const uint32_t avb = smem_u32(sAV);
        const uint32_t bhb = smem_u32(sBBh);
        const uint32_t blb = smem_u32(sBBl);
        uint32_t av[2][4];
#pragma unroll
        for (int mt = 0; mt < 2; ++mt)
            ldsm4(av[mt], avb + (uint32_t)((rowBase + mt * 16 + l15) * 32 + l16 * 16));
        uint32_t bbh[8][2], bbl[8][2];
#pragma unroll
        for (int p = 0; p < 4; ++p) {
            const uint32_t off = (uint32_t)((16 * p + l15) * 32 + l16 * 16);
            uint32_t r[4];
            ldsm4(r, bhb + off);
            bbh[2*p][0] = r[0]; bbh[2*p+1][0] = r[1];
            bbh[2*p][1] = r[2]; bbh[2*p+1][1] = r[3];
            ldsm4(r, blb + off);
            bbl[2*p][0] = r[0]; bbl[2*p+1][0] = r[1];
            bbl[2*p][1] = r[2]; bbl[2*p+1][1] = r[3];
        }
#pragma unroll
        for (int mt = 0; mt < 2; ++mt)
#pragma unroll
            for (int nt = 0; nt < 8; ++nt) {
                mma16816(C[mt][nt], av[mt], bbh[nt]);
                mma16816(C[mt][nt], av[mt], bbl[nt]);
            }
    }

    // ---- epilogue: descale + leaky -> smem fp32 tile -> store + stats ----
    __syncthreads();
    float* sC = (float*)smemc;                   // [128][SC_STRIDE] (34.8KB <= 64KB)
    const int fg = lane >> 2, ft2 = (lane & 3) * 2;
#pragma unroll
    for (int mt = 0; mt < 2; ++mt)
#pragma unroll
        for (int nt = 0; nt < 8; ++nt) {
            float* c = C[mt][nt];
#pragma unroll
            for (int i = 0; i < 4; ++i) {
                const float v = c[i] * INV_WSCALE;
                c[i] = (v > 0.f) ? v : LEAK * v;
            }
            const int r0 = rowBase + mt * 16 + fg;
            const int col = nt * 8 + ft2;
            *(float2*)&sC[r0 * SC_STRIDE + col]       = make_float2(c[0], c[1]);
            *(float2*)&sC[(r0 + 8) * SC_STRIDE + col] = make_float2(c[2], c[3]);
        }
    __syncthreads();

    if (rowOK) {
        const float4* rowp = (const float4*)(sC + tid * SC_STRIDE);
        if (OUT_PLANES) {
            uint4* d = (uint4*)(dstP + (size_t)(nBase + tid) * 64);
#pragma unroll
            for (int g = 0; g < 8; ++g) {
                const float4 v0 = rowp[2 * g], v1 = rowp[2 * g + 1];
                uint4 o;
                o.x = pack2h(v0.x, v0.y);
                o.y = pack2h(v0.z, v0.w);
                o.z = pack2h(v1.x, v1.y);
                o.w = pack2h(v1.z, v1.w);
                d[g] = o;
            }
        } else {
            float4* drow = (float4*)(dstF + (size_t)(nBase + tid) * CCH);
#pragma unroll
            for (int c4 = 0; c4 < 16; ++c4) drow[c4] = rowp[c4];
        }
    }

    {
        const int ch = tid >> 1, half = tid & 1;
        float s = 0.f, s2 = 0.f;
#pragma unroll 8
        for (int i = 0; i < 64; ++i) {
            const float v = sC[(half * 64 + i) * SC_STRIDE + ch];
            s += v; s2 += v * v;
        }
        s  += __shfl_xor_sync(0xffffffffu, s, 1);
        s2 += __shfl_xor_sync(0xffffffffu, s2, 1);
        if (!half) {
            atomicAdd(&g_sums[stage][ch], s);
            atomicAdd(&g_sumsq[stage][ch], s2);
        }
    }
}

// out = BN3(out) + BN1(y2); coefficients for stages 1,3 computed inline
__global__ __launch_bounds__(256)
void final_k(float* __restrict__ out, const float* __restrict__ y2,
             const float* __restrict__ g1_, const float* __restrict__ b1_,
             const float* __restrict__ g3_, const float* __restrict__ b3_,
             float invN, int total4)
{
    __shared__ float c1[64], s1[64], c3[64], s3[64];
    const int tid = threadIdx.x;
    if (tid < 64) {
        const float m1 = g_sums[1][tid] * invN;
        const float v1 = g_sumsq[1][tid] * invN - m1 * m1;
        const float a1 = g1_[tid] * rsqrtf(v1 + EPS_BN);
        c1[tid] = a1; s1[tid] = b1_[tid] - m1 * a1;
        const float m3 = g_sums[3][tid] * invN;
        const float v3 = g_sumsq[3][tid] * invN - m3 * m3;
        const float a3 = g3_[tid] * rsqrtf(v3 + EPS_BN);
        c3[tid] = a3; s3[tid] = b3_[tid] - m3 * a3;
    }
    __syncthreads();
    const int i = blockIdx.x * 256 + tid;
    if (i >= total4) return;
    float4 a = ((float4*)out)[i];
    const float4 b = ((const float4*)y2)[i];
    const int c = (i * 4) & 63;
    a.x = fmaf(a.x, c3[c + 0], s3[c + 0]) + fmaf(b.x, c1[c + 0], s1[c + 0]);
    a.y = fmaf(a.y, c3[c + 1], s3[c + 1]) + fmaf(b.y, c1[c + 1], s1[c + 1]);
    a.z = fmaf(a.z, c3[c + 2], s3[c + 2]) + fmaf(b.z, c1[c + 2], s1[c + 2]);
    a.w = fmaf(a.w, c3[c + 3], s3[c + 3]) + fmaf(b.w, c1[c + 3], s1[c + 3]);
    ((float4*)out)[i] = a;
}

// ---------------- launcher ----------------
extern "C" void kernel_launch(void* const* d_in, const int* in_sizes, int n_in,
                              void* d_out, int out_size)
{
    const float* features = (const float*)d_in[0];
    const float* w1   = (const float*)d_in[1];
    const float* w1_2 = (const float*)d_in[2];
    const float* w2   = (const float*)d_in[3];
    const float* w3   = (const float*)d_in[4];
    const float* g0   = (const float*)d_in[5];
    const float* b0   = (const float*)d_in[6];
    const float* g0_2 = (const float*)d_in[7];
    const float* b0_2 = (const float*)d_in[8];
    const float* g1   = (const float*)d_in[9];
    const float* b1   = (const float*)d_in[10];
    const float* g2   = (const float*)d_in[11];
    const float* b2   = (const float*)d_in[12];
    const int*   nbr13 = (const int*)d_in[13];
    const int*   nbr31 = (const int*)d_in[14];

    const int nTotal = in_sizes[0] / CCH;
    const float invN = 1.0f / (float)nTotal;
    const int grid   = (nTotal + TN - 1) / TN;
    const int gridS  = (nTotal + 255) / 256;

    cudaFuncSetAttribute(conv_mma_k<false, true>,
                         cudaFuncAttributeMaxDynamicSharedMemorySize, DSM_BYTES);
    cudaFuncSetAttribute(conv_mma_k<true, false>,
                         cudaFuncAttributeMaxDynamicSharedMemorySize, DSM_BYTES);

    float* bufB = nullptr;
    __half *fS = nullptr, *aS = nullptr;
    cudaGetSymbolAddress((void**)&bufB, g_bufB);
    cudaGetSymbolAddress((void**)&fS, g_fS);
    cudaGetSymbolAddress((void**)&aS, g_aS);
    float* out = (float*)d_out;

    zero_stats_k<<<1, 512>>>(nTotal);
    prep_plain_k<<<2 * KTAPS, 256>>>(w1, w2);
    split_k<<<gridS, 256>>>(features, fS, nTotal);

    // shortcut: conv(nbr13,w1)[planes,stats0] -> fold BN0 into w1_2 -> conv(nbr31)[fp32,stats1]
    conv_mma_k<false, true ><<<grid, NTHR, DSM_BYTES>>>(fS, nbr13, 0, nullptr, aS, nTotal, 0);
    prep_fold_k<<<KTAPS, 256>>>(w1_2, 1, 0, g0, b0, invN);
    conv_mma_k<true , false><<<grid, NTHR, DSM_BYTES>>>(aS, nbr31, 1, bufB, nullptr, nTotal, 1);

    // main: conv(nbr31,w2)[planes,stats2] -> fold BN2 into w3 -> conv(nbr13)[fp32,stats3]
    conv_mma_k<false, true ><<<grid, NTHR, DSM_BYTES>>>(fS, nbr31, 2, nullptr, aS, nTotal, 2);
    prep_fold_k<<<KTAPS, 256>>>(w3, 3, 2, g1, b1, invN);
    conv_mma_k<true , false><<<grid, NTHR, DSM_BYTES>>>(aS, nbr13, 3, out, nullptr, nTotal, 3);

    // out = BN3(out) + BN1(bufB)
    const int total4 = nTotal * CCH / 4;
    final_k<<<(total4 + 255) / 256, 256>>>(out, bufB, g0_2, b0_2, g2, b2, invN, total4);
}

// round 9
// speedup vs baseline: 48.5901x; 1.0295x over previous
#include <cuda_runtime.h>
#include <cuda_fp16.h>
#include <cstdint>

// ---------------- problem constants ----------------
#define NMAX   200000
#define CCH    64
#define KTAPS  9
#define TN     128          // rows per block (MMA M)
#define NTHR   128
#define LEAK   0.01f
#define EPS_BN 1e-5f
#define WSCALE 256.0f       // weight scaling (keeps fp16 lo-plane normal)
#define INV_WSCALE (1.0f / 256.0f)

// per-stage dynamic smem: A 16K | Bhi 8K | Blo 8K = 32K, double-buffered
#define OFF_BHI 16384
#define OFF_BLO 24576
#define STAGE_BYTES 32768
#define DSM_BYTES (2 * STAGE_BYTES)
#define SC_STRIDE 68        // epilogue fp32 tile stride (floats)

// ---------------- scratch (no cudaMalloc allowed) ----------------
__device__ float g_bufB[(size_t)NMAX * CCH];
// fp16 feature rows: [row][64 fp16]; row nTotal = zero pad
__device__ __half g_fS[((size_t)NMAX + 1) * 64];
__device__ __half g_aS[((size_t)NMAX + 1) * 64];
__device__ __half g_wHi[4 * KTAPS * 64 * 64];  // [tensor][tap][o][c], x256
__device__ __half g_wLo[4 * KTAPS * 64 * 64];
__device__ __half g_biasHi[4 * 64 * 16];       // [tensor][o*16 + tap], x256
__device__ __half g_biasLo[4 * 64 * 16];
__device__ float g_sums [4][CCH];
__device__ float g_sumsq[4][CCH];

// ---------------- helpers ----------------
__device__ __forceinline__ uint32_t smem_u32(const void* p) {
    uint32_t a;
    asm("{ .reg .u64 t; cvta.to.shared.u64 t, %1; cvt.u32.u64 %0, t; }" : "=r"(a) : "l"(p));
    return a;
}
__device__ __forceinline__ void ldsm4(uint32_t* r, uint32_t addr) {
    asm volatile("ldmatrix.sync.aligned.m8n8.x4.shared.b16 {%0,%1,%2,%3}, [%4];"
        : "=r"(r[0]), "=r"(r[1]), "=r"(r[2]), "=r"(r[3]) : "r"(addr));
}
__device__ __forceinline__ void mma16816(float* c, const uint32_t* a, const uint32_t* b) {
    asm volatile("mma.sync.aligned.m16n8k16.row.col.f32.f16.f16.f32 "
        "{%0,%1,%2,%3}, {%4,%5,%6,%7}, {%8,%9}, {%0,%1,%2,%3};"
        : "+f"(c[0]), "+f"(c[1]), "+f"(c[2]), "+f"(c[3])
        : "r"(a[0]), "r"(a[1]), "r"(a[2]), "r"(a[3]), "r"(b[0]), "r"(b[1]));
}
__device__ __forceinline__ void hsplit(float v, uint16_t &h, uint16_t &l) {
    __half hh = __float2half_rn(v);
    h = __half_as_ushort(hh);
    l = __half_as_ushort(__float2half_rn(v - __half2float(hh)));
}
__device__ __forceinline__ uint32_t pack2h(float a, float b) {
    __half2 h = __floats2half2_rn(a, b);
    return *(uint32_t*)&h;
}

// ---------------- aux kernels ----------------
__global__ void zero_stats_k(int nTotal) {
    const int i = threadIdx.x;   // 512
    if (i < 256) ((float*)g_sums)[i] = 0.f;
    else ((float*)g_sumsq)[i - 256] = 0.f;
#pragma unroll
    for (int j = 0; j < 4; ++j) {
        ((uint32_t*)g_biasHi)[i + j * 512] = 0u;
        ((uint32_t*)g_biasLo)[i + j * 512] = 0u;
    }
    if (i < 32) ((uint32_t*)(g_fS + (size_t)nTotal * 64))[i] = 0u;
    else if (i < 64) ((uint32_t*)(g_aS + (size_t)nTotal * 64))[i - 32] = 0u;
}

// plain weights [9][c][o] -> fp16 planes [tensor][tap][o][c] x256 (tensors 0,2)
__global__ void prep_plain_k(const float* __restrict__ w1, const float* __restrict__ w2) {
    const int t = (blockIdx.x < KTAPS) ? 0 : 2;
    const int k = blockIdx.x % KTAPS;
    const float* src = ((t == 0) ? w1 : w2) + k * 4096;
    __half* dh = g_wHi + (size_t)(t * KTAPS + k) * 4096;
    __half* dl = g_wLo + (size_t)(t * KTAPS + k) * 4096;
#pragma unroll
    for (int i = 0; i < 16; ++i) {
        const int j = threadIdx.x + i * 256;     // j = c*64 + o
        const int c = j >> 6, o = j & 63;
        uint16_t h, l;
        hsplit(src[j] * WSCALE, h, l);
        dh[o * 64 + c] = __ushort_as_half(h);
        dl[o * 64 + c] = __ushort_as_half(l);
    }
}

// fold BN(stage) into weights: W' = 256*scale[c]*W; bias_k[o] = 256*sum_c shift[c]*W[c,o]
__global__ void prep_fold_k(const float* __restrict__ w, int tensor, int stage,
                            const float* __restrict__ gamma,
                            const float* __restrict__ beta, float invN) {
    __shared__ float sc[64], sh[64];
    const int k = blockIdx.x, tid = threadIdx.x;
    if (tid < 64) {
        const float m = g_sums[stage][tid] * invN;
        const float v = g_sumsq[stage][tid] * invN - m * m;
        const float a = gamma[tid] * rsqrtf(v + EPS_BN);
        sc[tid] = a;
        sh[tid] = beta[tid] - m * a;
    }
    __syncthreads();
    const float* src = w + (size_t)k * 4096;
    __half* dh = g_wHi + (size_t)(tensor * KTAPS + k) * 4096;
    __half* dl = g_wLo + (size_t)(tensor * KTAPS + k) * 4096;
#pragma unroll
    for (int i = 0; i < 16; ++i) {
        const int j = tid + i * 256;             // j = c*64 + o
        const int c = j >> 6, o = j & 63;
        uint16_t h, l;
        hsplit(sc[c] * src[j] * WSCALE, h, l);
        dh[o * 64 + c] = __ushort_as_half(h);
        dl[o * 64 + c] = __ushort_as_half(l);
    }
    if (tid < 64) {
        float s = 0.f;
#pragma unroll 8
        for (int c = 0; c < 64; ++c) s += sh[c] * src[c * 64 + tid];
        uint16_t h, l;
        hsplit(s * WSCALE, h, l);
        g_biasHi[tensor * 1024 + tid * 16 + k] = __ushort_as_half(h);
        g_biasLo[tensor * 1024 + tid * 16 + k] = __ushort_as_half(l);
    }
}

// fp32 features -> fp16 rows (once)
__global__ __launch_bounds__(256)
void split_k(const float* __restrict__ src, __half* __restrict__ dst, int nTotal) {
    const int row = blockIdx.x * 256 + threadIdx.x;
    if (row >= nTotal) return;
    const float4* s = (const float4*)(src + (size_t)row * CCH);
    uint4* d = (uint4*)(dst + (size_t)row * 64);
#pragma unroll
    for (int g = 0; g < 8; ++g) {
        const float4 v0 = s[2 * g], v1 = s[2 * g + 1];
        uint4 o;
        o.x = pack2h(v0.x, v0.y);
        o.y = pack2h(v0.z, v0.w);
        o.z = pack2h(v1.x, v1.y);
        o.w = pack2h(v1.z, v1.w);
        d[g] = o;
    }
}

// ---------------- main conv kernel (mma.sync fp16 2-term, 2Mx2N warps) ----------------
template <bool HAS_BIAS, bool OUT_PLANES>
__global__ __launch_bounds__(NTHR, 3)
void conv_mma_k(const __half* __restrict__ src,   // [N+1][64] fp16
                const int* __restrict__ nbr, int wtIdx,
                float* __restrict__ dstF, __half* __restrict__ dstP,
                int nTotal, int stage)
{
    extern __shared__ __align__(128) char smemc[];
    __shared__ uint4 sAV[128][2];     // validity [128 rows][16 taps] fp16
    __shared__ uint4 sBBh[128];       // bias hi [64 o][16 taps] fp16
    __shared__ uint4 sBBl[128];

    const int tid   = threadIdx.x;
    const int lane  = tid & 31;
    const int wid   = tid >> 5;
    const int nBase = blockIdx.x * TN;
    const bool rowOK = (nBase + tid) < nTotal;

    const uint32_t sbase = smem_u32(smemc);
    // 2M x 2N warp grid: warp tile = 64 rows x 32 outch
    const int wm = wid & 1, wn = wid >> 1;
    const int rowBase = wm * 64;
    const int colBase = wn * 32;
    const int lsw = lane & 7, l15 = lane & 15, l16 = lane >> 4;
    const int rsw = tid & 7;

    // preload all 9 neighbor ids
    int nb[KTAPS];
#pragma unroll
    for (int k = 0; k < KTAPS; ++k)
        nb[k] = rowOK ? nbr[(size_t)(nBase + tid) * KTAPS + k] : nTotal;

    if (HAS_BIAS) {
        const uint32_t one = 0x3C00u;   // fp16 1.0
        uint32_t p[8];
#pragma unroll
        for (int i = 0; i < 8; ++i) {
            const uint32_t lo = (2 * i     < KTAPS && nb[2 * i]     < nTotal) ? one : 0u;
            const uint32_t hi = (2 * i + 1 < KTAPS && nb[2 * i + 1] < nTotal) ? one : 0u;
            p[i] = lo | (hi << 16);
        }
        sAV[tid][0] = make_uint4(p[0], p[1], p[2], p[3]);
        sAV[tid][1] = make_uint4(p[4], p[5], p[6], p[7]);
        sBBh[tid] = ((const uint4*)(g_biasHi + wtIdx * 1024))[tid];
        sBBl[tid] = ((const uint4*)(g_biasLo + wtIdx * 1024))[tid];
    }

    float C[4][4][4];
#pragma unroll
    for (int mt = 0; mt < 4; ++mt)
#pragma unroll
        for (int nt = 0; nt < 4; ++nt)
#pragma unroll
            for (int i = 0; i < 4; ++i) C[mt][nt][i] = 0.f;

    const __half* wHiT = g_wHi + (size_t)(wtIdx * KTAPS) * 4096;
    const __half* wLoT = g_wLo + (size_t)(wtIdx * KTAPS) * 4096;

    // ---- register staging: A only (random rows -> long L2 latency) ----
    uint4 pa[8];

    auto ldgA = [&](int k) {
        const uint4* arow = (const uint4*)(src + (size_t)nb[k] * 64);
#pragma unroll
        for (int g = 0; g < 8; ++g) pa[g] = arow[g];
    };
    // A from regs + B direct LDG->STS (B is L1/L2-hot: same addrs for all CTAs)
    auto stsTap = [&](int k, int s) {
        char* ab = smemc + s * STAGE_BYTES;
        char* aRow = ab + tid * 128;
#pragma unroll
        for (int g = 0; g < 8; ++g) {
            const int off = (g ^ rsw) << 4;
            *(uint4*)(aRow + off) = pa[g];
        }
        const uint4* bh4 = (const uint4*)(wHiT + (size_t)k * 4096);
        const uint4* bl4 = (const uint4*)(wLoT + (size_t)k * 4096);
#pragma unroll
        for (int i = 0; i < 4; ++i) {
            const int id = tid * 4 + i;          // 0..511 16B chunks
            const int n = id >> 3, kg = id & 7;
            const int so = (n * 64 + kg * 8) >> 3;   // uint4 index
            const int dofs = n * 128 + ((kg ^ (n & 7)) << 4);
            *(uint4*)(ab + OFF_BHI + dofs) = bh4[so];
            *(uint4*)(ab + OFF_BLO + dofs) = bl4[so];
        }
    };

    ldgA(0);
    stsTap(0, 0);

    for (int k = 0; k < KTAPS; ++k) {
        __syncthreads();                 // stage k&1 visible; stage (k+1)&1 free

        if (k < KTAPS - 1) ldgA(k + 1);  // LDG latency hides under MMAs below

        const uint32_t ab = sbase + (k & 1) * STAGE_BYTES;
#pragma unroll
        for (int q = 0; q < 4; ++q) {
            const int kg = 2 * q + l16;
            uint32_t a_[4][4];
#pragma unroll
            for (int mt = 0; mt < 4; ++mt) {
                const uint32_t off =
                    (uint32_t)((rowBase + mt * 16 + l15) * 128 + ((kg ^ lsw) << 4));
                ldsm4(a_[mt], ab + off);
            }
            uint32_t bh[4][2], bl[4][2];
#pragma unroll
            for (int p = 0; p < 2; ++p) {
                const uint32_t off =
                    (uint32_t)((colBase + 16 * p + l15) * 128 + ((kg ^ lsw) << 4));
                uint32_t r[4];
                ldsm4(r, ab + OFF_BHI + off);
                bh[2*p][0] = r[0]; bh[2*p+1][0] = r[1];
                bh[2*p][1] = r[2]; bh[2*p+1][1] = r[3];
                ldsm4(r, ab + OFF_BLO + off);
                bl[2*p][0] = r[0]; bl[2*p+1][0] = r[1];
                bl[2*p][1] = r[2]; bl[2*p+1][1] = r[3];
            }
#pragma unroll
            for (int mt = 0; mt < 4; ++mt)
#pragma unroll
                for (int nt = 0; nt < 4; ++nt) {
                    mma16816(C[mt][nt], a_[mt], bh[nt]);
                    mma16816(C[mt][nt], a_[mt], bl[nt]);
                }
        }

        if (k < KTAPS - 1) stsTap(k + 1, (k + 1) & 1);
    }

    // ---- bias MMA: C += V(128x16) * B(16x64), hi + lo ----
    if (HAS_BIAS) {
        const uint32_t avb = smem_u32(sAV);
        const uint32_t bhb = smem_u32(sBBh);
        const uint32_t blb = smem_u32(sBBl);
        uint32_t av[4][4];
#pragma unroll
        for (int mt = 0; mt < 4; ++mt)
            ldsm4(av[mt], avb + (uint32_t)((rowBase + mt * 16 + l15) * 32 + l16 * 16));
        uint32_t bbh[4][2], bbl[4][2];
#pragma unroll
        for (int p = 0; p < 2; ++p) {
            const uint32_t off = (uint32_t)((colBase + 16 * p + l15) * 32 + l16 * 16);
            uint32_t r[4];
            ldsm4(r, bhb + off);
            bbh[2*p][0] = r[0]; bbh[2*p+1][0] = r[1];
            bbh[2*p][1] = r[2]; bbh[2*p+1][1] = r[3];
            ldsm4(r, blb + off);
            bbl[2*p][0] = r[0]; bbl[2*p+1][0] = r[1];
            bbl[2*p][1] = r[2]; bbl[2*p+1][1] = r[3];
        }
#pragma unroll
        for (int mt = 0; mt < 4; ++mt)
#pragma unroll
            for (int nt = 0; nt < 4; ++nt) {
                mma16816(C[mt][nt], av[mt], bbh[nt]);
                mma16816(C[mt][nt], av[mt], bbl[nt]);
            }
    }

    // ---- epilogue: descale + leaky -> smem fp32 tile -> store + stats ----
    __syncthreads();
    float* sC = (float*)smemc;                   // [128][SC_STRIDE] (34.8KB <= 64KB)
    const int fg = lane >> 2, ft2 = (lane & 3) * 2;
#pragma unroll
    for (int mt = 0; mt < 4; ++mt)
#pragma unroll
        for (int nt = 0; nt < 4; ++nt) {
            float* c = C[mt][nt];
#pragma unroll
            for (int i = 0; i < 4; ++i) {
                const float v = c[i] * INV_WSCALE;
                c[i] = (v > 0.f) ? v : LEAK * v;
            }
            const int r0 = rowBase + mt * 16 + fg;
            const int col = colBase + nt * 8 + ft2;
            *(float2*)&sC[r0 * SC_STRIDE + col]       = make_float2(c[0], c[1]);
            *(float2*)&sC[(r0 + 8) * SC_STRIDE + col] = make_float2(c[2], c[3]);
        }
    __syncthreads();

    if (rowOK) {
        const float4* rowp = (const float4*)(sC + tid * SC_STRIDE);
        if (OUT_PLANES) {
            uint4* d = (uint4*)(dstP + (size_t)(nBase + tid) * 64);
#pragma unroll
            for (int g = 0; g < 8; ++g) {
                const float4 v0 = rowp[2 * g], v1 = rowp[2 * g + 1];
                uint4 o;
                o.x = pack2h(v0.x, v0.y);
                o.y = pack2h(v0.z, v0.w);
                o.z = pack2h(v1.x, v1.y);
                o.w = pack2h(v1.z, v1.w);
                d[g] = o;
            }
        } else {
            float4* drow = (float4*)(dstF + (size_t)(nBase + tid) * CCH);
#pragma unroll
            for (int c4 = 0; c4 < 16; ++c4) drow[c4] = rowp[c4];
        }
    }

    {
        const int ch = tid >> 1, half = tid & 1;
        float s = 0.f, s2 = 0.f;
#pragma unroll 8
        for (int i = 0; i < 64; ++i) {
            const float v = sC[(half * 64 + i) * SC_STRIDE + ch];
            s += v; s2 += v * v;
        }
        s  += __shfl_xor_sync(0xffffffffu, s, 1);
        s2 += __shfl_xor_sync(0xffffffffu, s2, 1);
        if (!half) {
            atomicAdd(&g_sums[stage][ch], s);
            atomicAdd(&g_sumsq[stage][ch], s2);
        }
    }
}

// out = BN3(out) + BN1(y2); coefficients for stages 1,3 computed inline
__global__ __launch_bounds__(256)
void final_k(float* __restrict__ out, const float* __restrict__ y2,
             const float* __restrict__ g1_, const float* __restrict__ b1_,
             const float* __restrict__ g3_, const float* __restrict__ b3_,
             float invN, int total4)
{
    __shared__ float c1[64], s1[64], c3[64], s3[64];
    const int tid = threadIdx.x;
    if (tid < 64) {
        const float m1 = g_sums[1][tid] * invN;
        const float v1 = g_sumsq[1][tid] * invN - m1 * m1;
        const float a1 = g1_[tid] * rsqrtf(v1 + EPS_BN);
        c1[tid] = a1; s1[tid] = b1_[tid] - m1 * a1;
        const float m3 = g_sums[3][tid] * invN;
        const float v3 = g_sumsq[3][tid] * invN - m3 * m3;
        const float a3 = g3_[tid] * rsqrtf(v3 + EPS_BN);
        c3[tid] = a3; s3[tid] = b3_[tid] - m3 * a3;
    }
    __syncthreads();
    const int i = blockIdx.x * 256 + tid;
    if (i >= total4) return;
    float4 a = ((float4*)out)[i];
    const float4 b = ((const float4*)y2)[i];
    const int c = (i * 4) & 63;
    a.x = fmaf(a.x, c3[c + 0], s3[c + 0]) + fmaf(b.x, c1[c + 0], s1[c + 0]);
    a.y = fmaf(a.y, c3[c + 1], s3[c + 1]) + fmaf(b.y, c1[c + 1], s1[c + 1]);
    a.z = fmaf(a.z, c3[c + 2], s3[c + 2]) + fmaf(b.z, c1[c + 2], s1[c + 2]);
    a.w = fmaf(a.w, c3[c + 3], s3[c + 3]) + fmaf(b.w, c1[c + 3], s1[c + 3]);
    ((float4*)out)[i] = a;
}

// ---------------- launcher ----------------
extern "C" void kernel_launch(void* const* d_in, const int* in_sizes, int n_in,
                              void* d_out, int out_size)
{
    const float* features = (const float*)d_in[0];
    const float* w1   = (const float*)d_in[1];
    const float* w1_2 = (const float*)d_in[2];
    const float* w2   = (const float*)d_in[3];
    const float* w3   = (const float*)d_in[4];
    const float* g0   = (const float*)d_in[5];
    const float* b0   = (const float*)d_in[6];
    const float* g0_2 = (const float*)d_in[7];
    const float* b0_2 = (const float*)d_in[8];
    const float* g1   = (const float*)d_in[9];
    const float* b1   = (const float*)d_in[10];
    const float* g2   = (const float*)d_in[11];
    const float* b2   = (const float*)d_in[12];
    const int*   nbr13 = (const int*)d_in[13];
    const int*   nbr31 = (const int*)d_in[14];

    const int nTotal = in_sizes[0] / CCH;
    const float invN = 1.0f / (float)nTotal;
    const int grid   = (nTotal + TN - 1) / TN;
    const int gridS  = (nTotal + 255) / 256;

    cudaFuncSetAttribute(conv_mma_k<false, true>,
                         cudaFuncAttributeMaxDynamicSharedMemorySize, DSM_BYTES);
    cudaFuncSetAttribute(conv_mma_k<true, false>,
                         cudaFuncAttributeMaxDynamicSharedMemorySize, DSM_BYTES);

    float* bufB = nullptr;
    __half *fS = nullptr, *aS = nullptr;
    cudaGetSymbolAddress((void**)&bufB, g_bufB);
    cudaGetSymbolAddress((void**)&fS, g_fS);
    cudaGetSymbolAddress((void**)&aS, g_aS);
    float* out = (float*)d_out;

    zero_stats_k<<<1, 512>>>(nTotal);
    prep_plain_k<<<2 * KTAPS, 256>>>(w1, w2);
    split_k<<<gridS, 256>>>(features, fS, nTotal);

    // shortcut: conv(nbr13,w1)[planes,stats0] -> fold BN0 into w1_2 -> conv(nbr31)[fp32,stats1]
    conv_mma_k<false, true ><<<grid, NTHR, DSM_BYTES>>>(fS, nbr13, 0, nullptr, aS, nTotal, 0);
    prep_fold_k<<<KTAPS, 256>>>(w1_2, 1, 0, g0, b0, invN);
    conv_mma_k<true , false><<<grid, NTHR, DSM_BYTES>>>(aS, nbr31, 1, bufB, nullptr, nTotal, 1);

    // main: conv(nbr31,w2)[planes,stats2] -> fold BN2 into w3 -> conv(nbr13)[fp32,stats3]
    conv_mma_k<false, true ><<<grid, NTHR, DSM_BYTES>>>(fS, nbr31, 2, nullptr, aS, nTotal, 2);
    prep_fold_k<<<KTAPS, 256>>>(w3, 3, 2, g1, b1, invN);
    conv_mma_k<true , false><<<grid, NTHR, DSM_BYTES>>>(aS, nbr13, 3, out, nullptr, nTotal, 3);

    // out = BN3(out) + BN1(bufB)
    const int total4 = nTotal * CCH / 4;
    final_k<<<(total4 + 255) / 256, 256>>>(out, bufB, g0_2, b0_2, g2, b2, invN, total4);
}

// round 10
// speedup vs baseline: 48.7330x; 1.0029x over previous
#include <cuda_runtime.h>
#include <cuda_fp16.h>
#include <cstdint>

// ---------------- problem constants ----------------
#define NMAX   200000
#define CCH    64
#define KTAPS  9
#define TN     128          // rows per block (MMA M)
#define NTHR   128
#define LEAK   0.01f
#define EPS_BN 1e-5f
#define WSCALE 256.0f       // weight scaling (keeps fp16 lo-plane normal)
#define INV_WSCALE (1.0f / 256.0f)

// per-stage dynamic smem: A 16K | Bhi 8K | Blo 8K = 32K, double-buffered
#define OFF_BHI 16384
#define OFF_BLO 24576
#define STAGE_BYTES 32768
#define DSM_BYTES (2 * STAGE_BYTES)
#define SC_STRIDE 68        // epilogue fp32 tile stride (floats)

// ---------------- scratch (no cudaMalloc allowed) ----------------
__device__ float g_bufB[(size_t)NMAX * CCH];
// fp16 feature rows: [row][64 fp16]; row nTotal = zero pad
__device__ __half g_fS[((size_t)NMAX + 1) * 64];
__device__ __half g_aS[((size_t)NMAX + 1) * 64];
__device__ __half g_wHi[4 * KTAPS * 64 * 64];  // [tensor][tap][o][c], x256
__device__ __half g_wLo[4 * KTAPS * 64 * 64];
__device__ __half g_biasHi[4 * 64 * 16];       // [tensor][o*16 + tap], x256
__device__ __half g_biasLo[4 * 64 * 16];
__device__ float g_sums [4][CCH];
__device__ float g_sumsq[4][CCH];

// ---------------- helpers ----------------
__device__ __forceinline__ uint32_t smem_u32(const void* p) {
    uint32_t a;
    asm("{ .reg .u64 t; cvta.to.shared.u64 t, %1; cvt.u32.u64 %0, t; }" : "=r"(a) : "l"(p));
    return a;
}
__device__ __forceinline__ void ldsm4(uint32_t* r, uint32_t addr) {
    asm volatile("ldmatrix.sync.aligned.m8n8.x4.shared.b16 {%0,%1,%2,%3}, [%4];"
        : "=r"(r[0]), "=r"(r[1]), "=r"(r[2]), "=r"(r[3]) : "r"(addr));
}
__device__ __forceinline__ void mma16816(float* c, const uint32_t* a, const uint32_t* b) {
    asm volatile("mma.sync.aligned.m16n8k16.row.col.f32.f16.f16.f32 "
        "{%0,%1,%2,%3}, {%4,%5,%6,%7}, {%8,%9}, {%0,%1,%2,%3};"
        : "+f"(c[0]), "+f"(c[1]), "+f"(c[2]), "+f"(c[3])
        : "r"(a[0]), "r"(a[1]), "r"(a[2]), "r"(a[3]), "r"(b[0]), "r"(b[1]));
}
__device__ __forceinline__ void hsplit(float v, uint16_t &h, uint16_t &l) {
    __half hh = __float2half_rn(v);
    h = __half_as_ushort(hh);
    l = __half_as_ushort(__float2half_rn(v - __half2float(hh)));
}
__device__ __forceinline__ uint32_t pack2h(float a, float b) {
    __half2 h = __floats2half2_rn(a, b);
    return *(uint32_t*)&h;
}

// ---------------- aux kernels ----------------
__global__ void zero_stats_k(int nTotal) {
    const int i = threadIdx.x;   // 512
    if (i < 256) ((float*)g_sums)[i] = 0.f;
    else ((float*)g_sumsq)[i - 256] = 0.f;
#pragma unroll
    for (int j = 0; j < 4; ++j) {
        ((uint32_t*)g_biasHi)[i + j * 512] = 0u;
        ((uint32_t*)g_biasLo)[i + j * 512] = 0u;
    }
    if (i < 32) ((uint32_t*)(g_fS + (size_t)nTotal * 64))[i] = 0u;
    else if (i < 64) ((uint32_t*)(g_aS + (size_t)nTotal * 64))[i - 32] = 0u;
}

// plain weights [9][c][o] -> fp16 planes [tensor][tap][o][c] x256 (tensors 0,2)
__global__ void prep_plain_k(const float* __restrict__ w1, const float* __restrict__ w2) {
    const int t = (blockIdx.x < KTAPS) ? 0 : 2;
    const int k = blockIdx.x % KTAPS;
    const float* src = ((t == 0) ? w1 : w2) + k * 4096;
    __half* dh = g_wHi + (size_t)(t * KTAPS + k) * 4096;
    __half* dl = g_wLo + (size_t)(t * KTAPS + k) * 4096;
#pragma unroll
    for (int i = 0; i < 16; ++i) {
        const int j = threadIdx.x + i * 256;     // j = c*64 + o
        const int c = j >> 6, o = j & 63;
        uint16_t h, l;
        hsplit(src[j] * WSCALE, h, l);
        dh[o * 64 + c] = __ushort_as_half(h);
        dl[o * 64 + c] = __ushort_as_half(l);
    }
}

// fold BN(stage) into weights: W' = 256*scale[c]*W; bias_k[o] = 256*sum_c shift[c]*W[c,o]
__global__ void prep_fold_k(const float* __restrict__ w, int tensor, int stage,
                            const float* __restrict__ gamma,
                            const float* __restrict__ beta, float invN) {
    __shared__ float sc[64], sh[64];
    const int k = blockIdx.x, tid = threadIdx.x;
    if (tid < 64) {
        const float m = g_sums[stage][tid] * invN;
        const float v = g_sumsq[stage][tid] * invN - m * m;
        const float a = gamma[tid] * rsqrtf(v + EPS_BN);
        sc[tid] = a;
        sh[tid] = beta[tid] - m * a;
    }
    __syncthreads();
    const float* src = w + (size_t)k * 4096;
    __half* dh = g_wHi + (size_t)(tensor * KTAPS + k) * 4096;
    __half* dl = g_wLo + (size_t)(tensor * KTAPS + k) * 4096;
#pragma unroll
    for (int i = 0; i < 16; ++i) {
        const int j = tid + i * 256;             // j = c*64 + o
        const int c = j >> 6, o = j & 63;
        uint16_t h, l;
        hsplit(sc[c] * src[j] * WSCALE, h, l);
        dh[o * 64 + c] = __ushort_as_half(h);
        dl[o * 64 + c] = __ushort_as_half(l);
    }
    if (tid < 64) {
        float s = 0.f;
#pragma unroll 8
        for (int c = 0; c < 64; ++c) s += sh[c] * src[c * 64 + tid];
        uint16_t h, l;
        hsplit(s * WSCALE, h, l);
        g_biasHi[tensor * 1024 + tid * 16 + k] = __ushort_as_half(h);
        g_biasLo[tensor * 1024 + tid * 16 + k] = __ushort_as_half(l);
    }
}

// fp32 features -> fp16 rows (once)
__global__ __launch_bounds__(256)
void split_k(const float* __restrict__ src, __half* __restrict__ dst, int nTotal) {
    const int row = blockIdx.x * 256 + threadIdx.x;
    if (row >= nTotal) return;
    const float4* s = (const float4*)(src + (size_t)row * CCH);
    uint4* d = (uint4*)(dst + (size_t)row * 64);
#pragma unroll
    for (int g = 0; g < 8; ++g) {
        const float4 v0 = s[2 * g], v1 = s[2 * g + 1];
        uint4 o;
        o.x = pack2h(v0.x, v0.y);
        o.y = pack2h(v0.z, v0.w);
        o.z = pack2h(v1.x, v1.y);
        o.w = pack2h(v1.z, v1.w);
        d[g] = o;
    }
}

// ---------------- main conv kernel (fp16 2-term, cooperative full-line gather) ----------------
template <bool HAS_BIAS, bool OUT_PLANES>
__global__ __launch_bounds__(NTHR, 3)
void conv_mma_k(const __half* __restrict__ src,   // [N+1][64] fp16
                const int* __restrict__ nbr, int wtIdx,
                float* __restrict__ dstF, __half* __restrict__ dstP,
                int nTotal, int stage)
{
    extern __shared__ __align__(128) char smemc[];
    __shared__ uint4 sBBh[128];       // bias hi [64 o][16 taps] fp16
    __shared__ uint4 sBBl[128];
    __shared__ int   sNbr[128 * KTAPS];  // neighbor ids, all rows x taps

    const int tid   = threadIdx.x;
    const int lane  = tid & 31;
    const int wid   = tid >> 5;
    const int nBase = blockIdx.x * TN;
    const bool rowOK = (nBase + tid) < nTotal;

    const uint32_t sbase = smem_u32(smemc);
    // 2M x 2N warp grid: warp tile = 64 rows x 32 outch
    const int wm = wid & 1, wn = wid >> 1;
    const int rowBase = wm * 64;
    const int colBase = wn * 32;
    const int lsw = lane & 7, l15 = lane & 15, l16 = lane >> 4;

    // neighbor table (coalesced fill; invalid rows -> pad index nTotal)
#pragma unroll
    for (int j = 0; j < KTAPS; ++j)
        sNbr[tid * KTAPS + j] = rowOK ? nbr[(size_t)(nBase + tid) * KTAPS + j] : nTotal;

    if (HAS_BIAS) {
        sBBh[tid] = ((const uint4*)(g_biasHi + wtIdx * 1024))[tid];
        sBBl[tid] = ((const uint4*)(g_biasLo + wtIdx * 1024))[tid];
    }

    float C[4][4][4];
#pragma unroll
    for (int mt = 0; mt < 4; ++mt)
#pragma unroll
        for (int nt = 0; nt < 4; ++nt)
#pragma unroll
            for (int i = 0; i < 4; ++i) C[mt][nt][i] = 0.f;

    const __half* wHiT = g_wHi + (size_t)(wtIdx * KTAPS) * 4096;
    const __half* wLoT = g_wLo + (size_t)(wtIdx * KTAPS) * 4096;

    // cooperative gather: 8 lanes per row, 4 rows per instruction (full 128B lines)
    const int gRow0  = (wid << 5) + (lane >> 3);   // +4 per it
    const int gChunk = lane & 7;
    uint4 pa[8];

    auto ldgA = [&](int k) {
#pragma unroll
        for (int it = 0; it < 8; ++it) {
            const int rl = gRow0 + (it << 2);
            const int nidx = sNbr[rl * KTAPS + k];
            pa[it] = *(const uint4*)(src + (size_t)nidx * 64 + (gChunk << 3));
        }
    };
    auto stsTap = [&](int k, int s) {
        char* ab = smemc + s * STAGE_BYTES;
#pragma unroll
        for (int it = 0; it < 8; ++it) {
            const int rl = gRow0 + (it << 2);
            *(uint4*)(ab + rl * 128 + ((gChunk ^ (rl & 7)) << 4)) = pa[it];
        }
        const uint4* bh4 = (const uint4*)(wHiT + (size_t)k * 4096);
        const uint4* bl4 = (const uint4*)(wLoT + (size_t)k * 4096);
#pragma unroll
        for (int i = 0; i < 4; ++i) {
            const int id = tid * 4 + i;          // 0..511 16B chunks
            const int n = id >> 3, kg = id & 7;
            const int so = (n * 64 + kg * 8) >> 3;   // uint4 index
            const int dofs = n * 128 + ((kg ^ (n & 7)) << 4);
            *(uint4*)(ab + OFF_BHI + dofs) = bh4[so];
            *(uint4*)(ab + OFF_BLO + dofs) = bl4[so];
        }
    };

    __syncthreads();                 // sNbr visible to all warps
    ldgA(0);
    stsTap(0, 0);

    for (int k = 0; k < KTAPS; ++k) {
        __syncthreads();             // stage k&1 visible; stage (k+1)&1 free

        if (k < KTAPS - 1) ldgA(k + 1);  // full-line LDGs hide under MMAs below

        const uint32_t ab = sbase + (k & 1) * STAGE_BYTES;
#pragma unroll
        for (int q = 0; q < 4; ++q) {
            const int kg = 2 * q + l16;
            uint32_t a_[4][4];
#pragma unroll
            for (int mt = 0; mt < 4; ++mt) {
                const uint32_t off =
                    (uint32_t)((rowBase + mt * 16 + l15) * 128 + ((kg ^ lsw) << 4));
                ldsm4(a_[mt], ab + off);
            }
            uint32_t bh[4][2], bl[4][2];
#pragma unroll
            for (int p = 0; p < 2; ++p) {
                const uint32_t off =
                    (uint32_t)((colBase + 16 * p + l15) * 128 + ((kg ^ lsw) << 4));
                uint32_t r[4];
                ldsm4(r, ab + OFF_BHI + off);
                bh[2*p][0] = r[0]; bh[2*p+1][0] = r[1];
                bh[2*p][1] = r[2]; bh[2*p+1][1] = r[3];
                ldsm4(r, ab + OFF_BLO + off);
                bl[2*p][0] = r[0]; bl[2*p+1][0] = r[1];
                bl[2*p][1] = r[2]; bl[2*p+1][1] = r[3];
            }
#pragma unroll
            for (int mt = 0; mt < 4; ++mt)
#pragma unroll
                for (int nt = 0; nt < 4; ++nt) {
                    mma16816(C[mt][nt], a_[mt], bh[nt]);
                    mma16816(C[mt][nt], a_[mt], bl[nt]);
                }
        }

        if (k < KTAPS - 1) stsTap(k + 1, (k + 1) & 1);
    }

    // ---- bias MMA: C += V(128x16) * B(16x64); V fragments built from sNbr ----
    if (HAS_BIAS) {
        // m16k16 A-fragment layout: reg j -> (row + 8*(j&1), col 2*(lane&3) + 8*(j>>1))
        uint32_t av[4][4];
        const int fr = lane >> 2, fc = (lane & 3) * 2;
#pragma unroll
        for (int mt = 0; mt < 4; ++mt) {
            const int r0 = rowBase + mt * 16 + fr;
            const int r1 = r0 + 8;
#pragma unroll
            for (int j = 0; j < 4; ++j) {
                const int rr = (j & 1) ? r1 : r0;
                const int c0 = fc + ((j >> 1) << 3);
                uint32_t lo = 0u, hi = 0u;
                if (c0     < KTAPS && sNbr[rr * KTAPS + c0]     < nTotal) lo = 0x3C00u;
                if (c0 + 1 < KTAPS && sNbr[rr * KTAPS + c0 + 1] < nTotal) hi = 0x3C00u;
                av[mt][j] = lo | (hi << 16);
            }
        }
        const uint32_t bhb = smem_u32(sBBh);
        const uint32_t blb = smem_u32(sBBl);
        uint32_t bbh[4][2], bbl[4][2];
#pragma unroll
        for (int p = 0; p < 2; ++p) {
            const uint32_t off = (uint32_t)((colBase + 16 * p + l15) * 32 + l16 * 16);
            uint32_t r[4];
            ldsm4(r, bhb + off);
            bbh[2*p][0] = r[0]; bbh[2*p+1][0] = r[1];
            bbh[2*p][1] = r[2]; bbh[2*p+1][1] = r[3];
            ldsm4(r, blb + off);
            bbl[2*p][0] = r[0]; bbl[2*p+1][0] = r[1];
            bbl[2*p][1] = r[2]; bbl[2*p+1][1] = r[3];
        }
#pragma unroll
        for (int mt = 0; mt < 4; ++mt)
#pragma unroll
            for (int nt = 0; nt < 4; ++nt) {
                mma16816(C[mt][nt], av[mt], bbh[nt]);
                mma16816(C[mt][nt], av[mt], bbl[nt]);
            }
    }

    // ---- epilogue: descale + leaky -> smem fp32 tile -> store + stats ----
    __syncthreads();
    float* sC = (float*)smemc;                   // [128][SC_STRIDE] (34.8KB <= 64KB)
    const int fg = lane >> 2, ft2 = (lane & 3) * 2;
#pragma unroll
    for (int mt = 0; mt < 4; ++mt)
#pragma unroll
        for (int nt = 0; nt < 4; ++nt) {
            float* c = C[mt][nt];
#pragma unroll
            for (int i = 0; i < 4; ++i) {
                const float v = c[i] * INV_WSCALE;
                c[i] = (v > 0.f) ? v : LEAK * v;
            }
            const int r0 = rowBase + mt * 16 + fg;
            const int col = colBase + nt * 8 + ft2;
            *(float2*)&sC[r0 * SC_STRIDE + col]       = make_float2(c[0], c[1]);
            *(float2*)&sC[(r0 + 8) * SC_STRIDE + col] = make_float2(c[2], c[3]);
        }
    __syncthreads();

    if (rowOK) {
        const float4* rowp = (const float4*)(sC + tid * SC_STRIDE);
        if (OUT_PLANES) {
            uint4* d = (uint4*)(dstP + (size_t)(nBase + tid) * 64);
#pragma unroll
            for (int g = 0; g < 8; ++g) {
                const float4 v0 = rowp[2 * g], v1 = rowp[2 * g + 1];
                uint4 o;
                o.x = pack2h(v0.x, v0.y);
                o.y = pack2h(v0.z, v0.w);
                o.z = pack2h(v1.x, v1.y);
                o.w = pack2h(v1.z, v1.w);
                d[g] = o;
            }
        } else {
            float4* drow = (float4*)(dstF + (size_t)(nBase + tid) * CCH);
#pragma unroll
            for (int c4 = 0; c4 < 16; ++c4) drow[c4] = rowp[c4];
        }
    }

    {
        const int ch = tid >> 1, half = tid & 1;
        float s = 0.f, s2 = 0.f;
#pragma unroll 8
        for (int i = 0; i < 64; ++i) {
            const float v = sC[(half * 64 + i) * SC_STRIDE + ch];
            s += v; s2 += v * v;
        }
        s  += __shfl_xor_sync(0xffffffffu, s, 1);
        s2 += __shfl_xor_sync(0xffffffffu, s2, 1);
        if (!half) {
            atomicAdd(&g_sums[stage][ch], s);
            atomicAdd(&g_sumsq[stage][ch], s2);
        }
    }
}

// out = BN3(out) + BN1(y2); coefficients for stages 1,3 computed inline
__global__ __launch_bounds__(256)
void final_k(float* __restrict__ out, const float* __restrict__ y2,
             const float* __restrict__ g1_, const float* __restrict__ b1_,
             const float* __restrict__ g3_, const float* __restrict__ b3_,
             float invN, int total4)
{
    __shared__ float c1[64], s1[64], c3[64], s3[64];
    const int tid = threadIdx.x;
    if (tid < 64) {
        const float m1 = g_sums[1][tid] * invN;
        const float v1 = g_sumsq[1][tid] * invN - m1 * m1;
        const float a1 = g1_[tid] * rsqrtf(v1 + EPS_BN);
        c1[tid] = a1; s1[tid] = b1_[tid] - m1 * a1;
        const float m3 = g_sums[3][tid] * invN;
        const float v3 = g_sumsq[3][tid] * invN - m3 * m3;
        const float a3 = g3_[tid] * rsqrtf(v3 + EPS_BN);
        c3[tid] = a3; s3[tid] = b3_[tid] - m3 * a3;
    }
    __syncthreads();
    const int i = blockIdx.x * 256 + tid;
    if (i >= total4) return;
    float4 a = ((float4*)out)[i];
    const float4 b = ((const float4*)y2)[i];
    const int c = (i * 4) & 63;
    a.x = fmaf(a.x, c3[c + 0], s3[c + 0]) + fmaf(b.x, c1[c + 0], s1[c + 0]);
    a.y = fmaf(a.y, c3[c + 1], s3[c + 1]) + fmaf(b.y, c1[c + 1], s1[c + 1]);
    a.z = fmaf(a.z, c3[c + 2], s3[c + 2]) + fmaf(b.z, c1[c + 2], s1[c + 2]);
    a.w = fmaf(a.w, c3[c + 3], s3[c + 3]) + fmaf(b.w, c1[c + 3], s1[c + 3]);
    ((float4*)out)[i] = a;
}

// ---------------- launcher ----------------
extern "C" void kernel_launch(void* const* d_in, const int* in_sizes, int n_in,
                              void* d_out, int out_size)
{
    const float* features = (const float*)d_in[0];
    const float* w1   = (const float*)d_in[1];
    const float* w1_2 = (const float*)d_in[2];
    const float* w2   = (const float*)d_in[3];
    const float* w3   = (const float*)d_in[4];
    const float* g0   = (const float*)d_in[5];
    const float* b0   = (const float*)d_in[6];
    const float* g0_2 = (const float*)d_in[7];
    const float* b0_2 = (const float*)d_in[8];
    const float* g1   = (const float*)d_in[9];
    const float* b1   = (const float*)d_in[10];
    const float* g2   = (const float*)d_in[11];
    const float* b2   = (const float*)d_in[12];
    const int*   nbr13 = (const int*)d_in[13];
    const int*   nbr31 = (const int*)d_in[14];

    const int nTotal = in_sizes[0] / CCH;
    const float invN = 1.0f / (float)nTotal;
    const int grid   = (nTotal + TN - 1) / TN;
    const int gridS  = (nTotal + 255) / 256;

    cudaFuncSetAttribute(conv_mma_k<false, true>,
                         cudaFuncAttributeMaxDynamicSharedMemorySize, DSM_BYTES);
    cudaFuncSetAttribute(conv_mma_k<true, false>,
                         cudaFuncAttributeMaxDynamicSharedMemorySize, DSM_BYTES);

    float* bufB = nullptr;
    __half *fS = nullptr, *aS = nullptr;
    cudaGetSymbolAddress((void**)&bufB, g_bufB);
    cudaGetSymbolAddress((void**)&fS, g_fS);
    cudaGetSymbolAddress((void**)&aS, g_aS);
    float* out = (float*)d_out;

    zero_stats_k<<<1, 512>>>(nTotal);
    prep_plain_k<<<2 * KTAPS, 256>>>(w1, w2);
    split_k<<<gridS, 256>>>(features, fS, nTotal);

    // shortcut: conv(nbr13,w1)[planes,stats0] -> fold BN0 into w1_2 -> conv(nbr31)[fp32,stats1]
    conv_mma_k<false, true ><<<grid, NTHR, DSM_BYTES>>>(fS, nbr13, 0, nullptr, aS, nTotal, 0);
    prep_fold_k<<<KTAPS, 256>>>(w1_2, 1, 0, g0, b0, invN);
    conv_mma_k<true , false><<<grid, NTHR, DSM_BYTES>>>(aS, nbr31, 1, bufB, nullptr, nTotal, 1);

    // main: conv(nbr31,w2)[planes,stats2] -> fold BN2 into w3 -> conv(nbr13,w3)[fp32,stats3]
    conv_mma_k<false, true ><<<grid, NTHR, DSM_BYTES>>>(fS, nbr31, 2, nullptr, aS, nTotal, 2);
    prep_fold_k<<<KTAPS, 256>>>(w3, 3, 2, g1, b1, invN);
    conv_mma_k<true , false><<<grid, NTHR, DSM_BYTES>>>(aS, nbr13, 3, out, nullptr, nTotal, 3);

    // out = BN3(out) + BN1(bufB)
    const int total4 = nTotal * CCH / 4;
    final_k<<<(total4 + 255) / 256, 256>>>(out, bufB, g0_2, b0_2, g2, b2, invN, total4);
}

// round 11
// speedup vs baseline: 62.0002x; 1.2722x over previous
#include <cuda_runtime.h>
#include <cuda_fp16.h>
#include <cstdint>

// ---------------- problem constants ----------------
#define NMAX   200000
#define CCH    64
#define KTAPS  9
#define TN     128          // rows per block (MMA M)
#define NTHR   128
#define LEAK   0.01f
#define EPS_BN 1e-5f
#define WSCALE 256.0f       // weight scaling (keeps fp16 lo-plane normal)
#define INV_WSCALE (1.0f / 256.0f)

// dynamic smem: A stage 16K x2 (compute) OR fp32 epilogue tile 34816B
#define STAGE_BYTES 16384
#define DSM_BYTES 34816
#define SC_STRIDE 68        // epilogue fp32 tile stride (floats)

// B fragment layout: halves per tap = 4q * (2wn*4c) chunks * 32 lanes * 8 = 8192
#define FRAG_TAP_HALVES   8192
#define FRAG_TENSOR_HALVES (KTAPS * FRAG_TAP_HALVES)   // 73728

// ---------------- scratch (no cudaMalloc allowed) ----------------
__device__ float g_bufB[(size_t)NMAX * CCH];
// fp16 feature rows: [row][64 fp16]; row nTotal = zero pad
__device__ __half g_fS[((size_t)NMAX + 1) * 64];
__device__ __half g_aS[((size_t)NMAX + 1) * 64];
__device__ __half g_wFrag[4 * FRAG_TENSOR_HALVES];   // B in per-lane MMA fragment layout
__device__ __half g_biasHi[4 * 64 * 16];             // [tensor][o*16 + tap], x256
__device__ __half g_biasLo[4 * 64 * 16];
__device__ float g_sums [4][CCH];
__device__ float g_sumsq[4][CCH];

// ---------------- helpers ----------------
__device__ __forceinline__ uint32_t smem_u32(const void* p) {
    uint32_t a;
    asm("{ .reg .u64 t; cvta.to.shared.u64 t, %1; cvt.u32.u64 %0, t; }" : "=r"(a) : "l"(p));
    return a;
}
__device__ __forceinline__ void ldsm4(uint32_t* r, uint32_t addr) {
    asm volatile("ldmatrix.sync.aligned.m8n8.x4.shared.b16 {%0,%1,%2,%3}, [%4];"
        : "=r"(r[0]), "=r"(r[1]), "=r"(r[2]), "=r"(r[3]) : "r"(addr));
}
__device__ __forceinline__ void mma16816(float* c, const uint32_t* a, const uint32_t* b) {
    asm volatile("mma.sync.aligned.m16n8k16.row.col.f32.f16.f16.f32 "
        "{%0,%1,%2,%3}, {%4,%5,%6,%7}, {%8,%9}, {%0,%1,%2,%3};"
        : "+f"(c[0]), "+f"(c[1]), "+f"(c[2]), "+f"(c[3])
        : "r"(a[0]), "r"(a[1]), "r"(a[2]), "r"(a[3]), "r"(b[0]), "r"(b[1]));
}
__device__ __forceinline__ void hsplit(float v, uint16_t &h, uint16_t &l) {
    __half hh = __float2half_rn(v);
    h = __half_as_ushort(hh);
    l = __half_as_ushort(__float2half_rn(v - __half2float(hh)));
}
__device__ __forceinline__ uint32_t pack2h(float a, float b) {
    __half2 h = __floats2half2_rn(a, b);
    return *(uint32_t*)&h;
}

// ---------------- aux kernels ----------------
__global__ void zero_stats_k(int nTotal) {
    const int i = threadIdx.x;   // 512
    if (i < 256) ((float*)g_sums)[i] = 0.f;
    else ((float*)g_sumsq)[i - 256] = 0.f;
#pragma unroll
    for (int j = 0; j < 4; ++j) {
        ((uint32_t*)g_biasHi)[i + j * 512] = 0u;
        ((uint32_t*)g_biasLo)[i + j * 512] = 0u;
    }
    if (i < 32) ((uint32_t*)(g_fS + (size_t)nTotal * 64))[i] = 0u;
    else if (i < 64) ((uint32_t*)(g_aS + (size_t)nTotal * 64))[i - 32] = 0u;
}

// Build one packed b16x2 frag reg from the scaled weight plane.
// P[k][n] = plane(src[k*64+n] * scale_k * WSCALE); reg = {P[k][n], P[k+1][n]}.
__device__ __forceinline__ uint32_t frag_reg(const float* __restrict__ src,
                                             const float* __restrict__ sck,
                                             int kk, int nn, int plane) {
    const float s0 = sck ? sck[kk] : 1.f;
    const float s1 = sck ? sck[kk + 1] : 1.f;
    uint16_t h0, l0, h1, l1;
    hsplit(src[kk * 64 + nn] * s0 * WSCALE, h0, l0);
    hsplit(src[(kk + 1) * 64 + nn] * s1 * WSCALE, h1, l1);
    const uint16_t a = plane ? l0 : h0;
    const uint16_t b = plane ? l1 : h1;
    return (uint32_t)a | ((uint32_t)b << 16);
}

__device__ __forceinline__ void write_frags(const float* __restrict__ src,
                                            const float* __restrict__ sck,
                                            __half* __restrict__ dstTap, int tid) {
#pragma unroll
    for (int i = 0; i < 4; ++i) {
        const int idx = tid + i * 256;           // 0..1023 uint4 slots
        const int lane = idx & 31;
        const int chunk = idx >> 5;              // 0..31: q*8 + wn*4 + c
        const int q = chunk >> 3, wn = (chunk >> 2) & 1, c = chunk & 3;
        const int plane = c >> 1, p = c & 1;
        const int m = lane & 3, nr = lane >> 2;
        const int k0 = 16 * q;
        const int n0 = wn * 32 + 16 * p + nr;
        uint4 o;
        o.x = frag_reg(src, sck, k0 + 2 * m,     n0,     plane);
        o.y = frag_reg(src, sck, k0 + 2 * m,     n0 + 8, plane);
        o.z = frag_reg(src, sck, k0 + 8 + 2 * m, n0,     plane);
        o.w = frag_reg(src, sck, k0 + 8 + 2 * m, n0 + 8, plane);
        ((uint4*)dstTap)[idx] = o;
    }
}

// plain weights [9][c][o] -> fragment layout (tensors 0 and 2)
__global__ void prep_plain_k(const float* __restrict__ w1, const float* __restrict__ w2) {
    const int t = (blockIdx.x < KTAPS) ? 0 : 2;
    const int k = blockIdx.x % KTAPS;
    const float* src = ((t == 0) ? w1 : w2) + k * 4096;
    __half* dst = g_wFrag + (size_t)t * FRAG_TENSOR_HALVES + (size_t)k * FRAG_TAP_HALVES;
    write_frags(src, nullptr, dst, threadIdx.x);
}

// fold BN(stage) into weights -> fragment layout; bias_k[o] = 256*sum_c shift[c]*W[c,o]
__global__ void prep_fold_k(const float* __restrict__ w, int tensor, int stage,
                            const float* __restrict__ gamma,
                            const float* __restrict__ beta, float invN) {
    __shared__ float sc[64], sh[64];
    const int k = blockIdx.x, tid = threadIdx.x;
    if (tid < 64) {
        const float m = g_sums[stage][tid] * invN;
        const float v = g_sumsq[stage][tid] * invN - m * m;
        const float a = gamma[tid] * rsqrtf(v + EPS_BN);
        sc[tid] = a;
        sh[tid] = beta[tid] - m * a;
    }
    __syncthreads();
    const float* src = w + (size_t)k * 4096;
    __half* dst = g_wFrag + (size_t)tensor * FRAG_TENSOR_HALVES + (size_t)k * FRAG_TAP_HALVES;
    write_frags(src, sc, dst, tid);
    if (tid < 64) {
        float s = 0.f;
#pragma unroll 8
        for (int c = 0; c < 64; ++c) s += sh[c] * src[c * 64 + tid];
        uint16_t h, l;
        hsplit(s * WSCALE, h, l);
        g_biasHi[tensor * 1024 + tid * 16 + k] = __ushort_as_half(h);
        g_biasLo[tensor * 1024 + tid * 16 + k] = __ushort_as_half(l);
    }
}

// fp32 features -> fp16 rows (once)
__global__ __launch_bounds__(256)
void split_k(const float* __restrict__ src, __half* __restrict__ dst, int nTotal) {
    const int row = blockIdx.x * 256 + threadIdx.x;
    if (row >= nTotal) return;
    const float4* s = (const float4*)(src + (size_t)row * CCH);
    uint4* d = (uint4*)(dst + (size_t)row * 64);
#pragma unroll
    for (int g = 0; g < 8; ++g) {
        const float4 v0 = s[2 * g], v1 = s[2 * g + 1];
        uint4 o;
        o.x = pack2h(v0.x, v0.y);
        o.y = pack2h(v0.z, v0.w);
        o.z = pack2h(v1.x, v1.y);
        o.w = pack2h(v1.z, v1.w);
        d[g] = o;
    }
}

// ---------------- main conv kernel (fp16 2-term, B direct from fragment gmem) ----------------
template <bool HAS_BIAS, bool OUT_PLANES>
__global__ __launch_bounds__(NTHR, 3)
void conv_mma_k(const __half* __restrict__ src,   // [N+1][64] fp16
                const int* __restrict__ nbr, int wtIdx,
                float* __restrict__ dstF, __half* __restrict__ dstP,
                int nTotal, int stage)
{
    extern __shared__ __align__(128) char smemc[];
    __shared__ uint4 sBBh[128];       // bias hi [64 o][16 taps] fp16
    __shared__ uint4 sBBl[128];
    __shared__ int   sNbr[128 * KTAPS];  // neighbor ids, all rows x taps

    const int tid   = threadIdx.x;
    const int lane  = tid & 31;
    const int wid   = tid >> 5;
    const int nBase = blockIdx.x * TN;
    const bool rowOK = (nBase + tid) < nTotal;

    const uint32_t sbase = smem_u32(smemc);
    // 2M x 2N warp grid: warp tile = 64 rows x 32 outch
    const int wm = wid & 1, wn = wid >> 1;
    const int rowBase = wm * 64;
    const int colBase = wn * 32;
    const int lsw = lane & 7, l15 = lane & 15, l16 = lane >> 4;

    // neighbor table (coalesced fill; invalid rows -> pad index nTotal)
#pragma unroll
    for (int j = 0; j < KTAPS; ++j)
        sNbr[tid * KTAPS + j] = rowOK ? nbr[(size_t)(nBase + tid) * KTAPS + j] : nTotal;

    if (HAS_BIAS) {
        sBBh[tid] = ((const uint4*)(g_biasHi + wtIdx * 1024))[tid];
        sBBl[tid] = ((const uint4*)(g_biasLo + wtIdx * 1024))[tid];
    }

    float C[4][4][4];
#pragma unroll
    for (int mt = 0; mt < 4; ++mt)
#pragma unroll
        for (int nt = 0; nt < 4; ++nt)
#pragma unroll
            for (int i = 0; i < 4; ++i) C[mt][nt][i] = 0.f;

    // B fragments: [tap][q][wn][chunk][lane] uint4
    const uint4* bF = (const uint4*)(g_wFrag + (size_t)wtIdx * FRAG_TENSOR_HALVES) + lane;

    // cooperative gather: 8 lanes per row, 4 rows per instruction (full 128B lines)
    const int gRow0  = (wid << 5) + (lane >> 3);   // +4 per it
    const int gChunk = lane & 7;
    uint4 pa[8];

    auto ldgA = [&](int k) {
#pragma unroll
        for (int it = 0; it < 8; ++it) {
            const int rl = gRow0 + (it << 2);
            const int nidx = sNbr[rl * KTAPS + k];
            pa[it] = *(const uint4*)(src + (size_t)nidx * 64 + (gChunk << 3));
        }
    };
    auto stsA = [&](int s) {
        char* ab = smemc + s * STAGE_BYTES;
#pragma unroll
        for (int it = 0; it < 8; ++it) {
            const int rl = gRow0 + (it << 2);
            *(uint4*)(ab + rl * 128 + ((gChunk ^ (rl & 7)) << 4)) = pa[it];
        }
    };

    __syncthreads();                 // sNbr visible to all warps
    ldgA(0);
    stsA(0);

    for (int k = 0; k < KTAPS; ++k) {
        __syncthreads();             // stage k&1 visible; stage (k+1)&1 free

        if (k < KTAPS - 1) ldgA(k + 1);  // full-line LDGs hide under MMAs below

        const uint32_t ab = sbase + (k & 1) * STAGE_BYTES;
#pragma unroll
        for (int q = 0; q < 4; ++q) {
            const int kg = 2 * q + l16;
            uint32_t a_[4][4];
#pragma unroll
            for (int mt = 0; mt < 4; ++mt) {
                const uint32_t off =
                    (uint32_t)((rowBase + mt * 16 + l15) * 128 + ((kg ^ lsw) << 4));
                ldsm4(a_[mt], ab + off);
            }
            // B fragments direct from gmem (L1-hot, fully coalesced)
            const uint4* bq = bF + (size_t)(((k * 4 + q) * 2 + wn) * 4) * 32;
            const uint4 f0 = bq[0], f1 = bq[32], f2 = bq[64], f3 = bq[96];
            uint32_t bh[4][2], bl[4][2];
            bh[0][0] = f0.x; bh[1][0] = f0.y; bh[0][1] = f0.z; bh[1][1] = f0.w;
            bh[2][0] = f1.x; bh[3][0] = f1.y; bh[2][1] = f1.z; bh[3][1] = f1.w;
            bl[0][0] = f2.x; bl[1][0] = f2.y; bl[0][1] = f2.z; bl[1][1] = f2.w;
            bl[2][0] = f3.x; bl[3][0] = f3.y; bl[2][1] = f3.z; bl[3][1] = f3.w;
#pragma unroll
            for (int mt = 0; mt < 4; ++mt)
#pragma unroll
                for (int nt = 0; nt < 4; ++nt) {
                    mma16816(C[mt][nt], a_[mt], bh[nt]);
                    mma16816(C[mt][nt], a_[mt], bl[nt]);
                }
        }

        if (k < KTAPS - 1) stsA((k + 1) & 1);
    }

    // ---- bias MMA: C += V(128x16) * B(16x64); V fragments built from sNbr ----
    if (HAS_BIAS) {
        // m16k16 A-fragment layout: reg j -> (row + 8*(j&1), col 2*(lane&3) + 8*(j>>1))
        uint32_t av[4][4];
        const int fr = lane >> 2, fc = (lane & 3) * 2;
#pragma unroll
        for (int mt = 0; mt < 4; ++mt) {
            const int r0 = rowBase + mt * 16 + fr;
            const int r1 = r0 + 8;
#pragma unroll
            for (int j = 0; j < 4; ++j) {
                const int rr = (j & 1) ? r1 : r0;
                const int c0 = fc + ((j >> 1) << 3);
                uint32_t lo = 0u, hi = 0u;
                if (c0     < KTAPS && sNbr[rr * KTAPS + c0]     < nTotal) lo = 0x3C00u;
                if (c0 + 1 < KTAPS && sNbr[rr * KTAPS + c0 + 1] < nTotal) hi = 0x3C00u;
                av[mt][j] = lo | (hi << 16);
            }
        }
        const uint32_t bhb = smem_u32(sBBh);
        const uint32_t blb = smem_u32(sBBl);
        uint32_t bbh[4][2], bbl[4][2];
#pragma unroll
        for (int p = 0; p < 2; ++p) {
            const uint32_t off = (uint32_t)((colBase + 16 * p + l15) * 32 + l16 * 16);
            uint32_t r[4];
            ldsm4(r, bhb + off);
            bbh[2*p][0] = r[0]; bbh[2*p+1][0] = r[1];
            bbh[2*p][1] = r[2]; bbh[2*p+1][1] = r[3];
            ldsm4(r, blb + off);
            bbl[2*p][0] = r[0]; bbl[2*p+1][0] = r[1];
            bbl[2*p][1] = r[2]; bbl[2*p+1][1] = r[3];
        }
#pragma unroll
        for (int mt = 0; mt < 4; ++mt)
#pragma unroll
            for (int nt = 0; nt < 4; ++nt) {
                mma16816(C[mt][nt], av[mt], bbh[nt]);
                mma16816(C[mt][nt], av[mt], bbl[nt]);
            }
    }

    // ---- epilogue: descale + leaky -> smem fp32 tile -> store + stats ----
    __syncthreads();
    float* sC = (float*)smemc;                   // [128][SC_STRIDE] = 34816B
    const int fg = lane >> 2, ft2 = (lane & 3) * 2;
#pragma unroll
    for (int mt = 0; mt < 4; ++mt)
#pragma unroll
        for (int nt = 0; nt < 4; ++nt) {
            float* c = C[mt][nt];
#pragma unroll
            for (int i = 0; i < 4; ++i) {
                const float v = c[i] * INV_WSCALE;
                c[i] = (v > 0.f) ? v : LEAK * v;
            }
            const int r0 = rowBase + mt * 16 + fg;
            const int col = colBase + nt * 8 + ft2;
            *(float2*)&sC[r0 * SC_STRIDE + col]       = make_float2(c[0], c[1]);
            *(float2*)&sC[(r0 + 8) * SC_STRIDE + col] = make_float2(c[2], c[3]);
        }
    __syncthreads();

    if (rowOK) {
        const float4* rowp = (const float4*)(sC + tid * SC_STRIDE);
        if (OUT_PLANES) {
            uint4* d = (uint4*)(dstP + (size_t)(nBase + tid) * 64);
#pragma unroll
            for (int g = 0; g < 8; ++g) {
                const float4 v0 = rowp[2 * g], v1 = rowp[2 * g + 1];
                uint4 o;
                o.x = pack2h(v0.x, v0.y);
                o.y = pack2h(v0.z, v0.w);
                o.z = pack2h(v1.x, v1.y);
                o.w = pack2h(v1.z, v1.w);
                d[g] = o;
            }
        } else {
            float4* drow = (float4*)(dstF + (size_t)(nBase + tid) * CCH);
#pragma unroll
            for (int c4 = 0; c4 < 16; ++c4) drow[c4] = rowp[c4];
        }
    }

    {
        const int ch = tid >> 1, half = tid & 1;
        float s = 0.f, s2 = 0.f;
#pragma unroll 8
        for (int i = 0; i < 64; ++i) {
            const float v = sC[(half * 64 + i) * SC_STRIDE + ch];
            s += v; s2 += v * v;
        }
        s  += __shfl_xor_sync(0xffffffffu, s, 1);
        s2 += __shfl_xor_sync(0xffffffffu, s2, 1);
        if (!half) {
            atomicAdd(&g_sums[stage][ch], s);
            atomicAdd(&g_sumsq[stage][ch], s2);
        }
    }
}

// out = BN3(out) + BN1(y2); coefficients for stages 1,3 computed inline
__global__ __launch_bounds__(256)
void final_k(float* __restrict__ out, const float* __restrict__ y2,
             const float* __restrict__ g1_, const float* __restrict__ b1_,
             const float* __restrict__ g3_, const float* __restrict__ b3_,
             float invN, int total4)
{
    __shared__ float c1[64], s1[64], c3[64], s3[64];
    const int tid = threadIdx.x;
    if (tid < 64) {
        const float m1 = g_sums[1][tid] * invN;
        const float v1 = g_sumsq[1][tid] * invN - m1 * m1;
        const float a1 = g1_[tid] * rsqrtf(v1 + EPS_BN);
        c1[tid] = a1; s1[tid] = b1_[tid] - m1 * a1;
        const float m3 = g_sums[3][tid] * invN;
        const float v3 = g_sumsq[3][tid] * invN - m3 * m3;
        const float a3 = g3_[tid] * rsqrtf(v3 + EPS_BN);
        c3[tid] = a3; s3[tid] = b3_[tid] - m3 * a3;
    }
    __syncthreads();
    const int i = blockIdx.x * 256 + tid;
    if (i >= total4) return;
    float4 a = ((float4*)out)[i];
    const float4 b = ((const float4*)y2)[i];
    const int c = (i * 4) & 63;
    a.x = fmaf(a.x, c3[c + 0], s3[c + 0]) + fmaf(b.x, c1[c + 0], s1[c + 0]);
    a.y = fmaf(a.y, c3[c + 1], s3[c + 1]) + fmaf(b.y, c1[c + 1], s1[c + 1]);
    a.z = fmaf(a.z, c3[c + 2], s3[c + 2]) + fmaf(b.z, c1[c + 2], s1[c + 2]);
    a.w = fmaf(a.w, c3[c + 3], s3[c + 3]) + fmaf(b.w, c1[c + 3], s1[c + 3]);
    ((float4*)out)[i] = a;
}

// ---------------- launcher ----------------
extern "C" void kernel_launch(void* const* d_in, const int* in_sizes, int n_in,
                              void* d_out, int out_size)
{
    const float* features = (const float*)d_in[0];
    const float* w1   = (const float*)d_in[1];
    const float* w1_2 = (const float*)d_in[2];
    const float* w2   = (const float*)d_in[3];
    const float* w3   = (const float*)d_in[4];
    const float* g0   = (const float*)d_in[5];
    const float* b0   = (const float*)d_in[6];
    const float* g0_2 = (const float*)d_in[7];
    const float* b0_2 = (const float*)d_in[8];
    const float* g1   = (const float*)d_in[9];
    const float* b1   = (const float*)d_in[10];
    const float* g2   = (const float*)d_in[11];
    const float* b2   = (const float*)d_in[12];
    const int*   nbr13 = (const int*)d_in[13];
    const int*   nbr31 = (const int*)d_in[14];

    const int nTotal = in_sizes[0] / CCH;
    const float invN = 1.0f / (float)nTotal;
    const int grid   = (nTotal + TN - 1) / TN;
    const int gridS  = (nTotal + 255) / 256;

    cudaFuncSetAttribute(conv_mma_k<false, true>,
                         cudaFuncAttributeMaxDynamicSharedMemorySize, DSM_BYTES);
    cudaFuncSetAttribute(conv_mma_k<true, false>,
                         cudaFuncAttributeMaxDynamicSharedMemorySize, DSM_BYTES);

    float* bufB = nullptr;
    __half *fS = nullptr, *aS = nullptr;
    cudaGetSymbolAddress((void**)&bufB, g_bufB);
    cudaGetSymbolAddress((void**)&fS, g_fS);
    cudaGetSymbolAddress((void**)&aS, g_aS);
    float* out = (float*)d_out;

    zero_stats_k<<<1, 512>>>(nTotal);
    prep_plain_k<<<2 * KTAPS, 256>>>(w1, w2);
    split_k<<<gridS, 256>>>(features, fS, nTotal);

    // shortcut: conv(nbr13,w1)[planes,stats0] -> fold BN0 into w1_2 -> conv(nbr31)[fp32,stats1]
    conv_mma_k<false, true ><<<grid, NTHR, DSM_BYTES>>>(fS, nbr13, 0, nullptr, aS, nTotal, 0);
    prep_fold_k<<<KTAPS, 256>>>(w1_2, 1, 0, g0, b0, invN);
    conv_mma_k<true , false><<<grid, NTHR, DSM_BYTES>>>(aS, nbr31, 1, bufB, nullptr, nTotal, 1);

    // main: conv(nbr31,w2)[planes,stats2] -> fold BN2 into w3 -> conv(nbr13,w3)[fp32,stats3]
    conv_mma_k<false, true ><<<grid, NTHR, DSM_BYTES>>>(fS, nbr31, 2, nullptr, aS, nTotal, 2);
    prep_fold_k<<<KTAPS, 256>>>(w3, 3, 2, g1, b1, invN);
    conv_mma_k<true , false><<<grid, NTHR, DSM_BYTES>>>(aS, nbr13, 3, out, nullptr, nTotal, 3);

    // out = BN3(out) + BN1(bufB)
    const int total4 = nTotal * CCH / 4;
    final_k<<<(total4 + 255) / 256, 256>>>(out, bufB, g0_2, b0_2, g2, b2, invN, total4);
}